// round 12
// baseline (speedup 1.0000x reference)
#include <cuda_runtime.h>
#include <cuda_bf16.h>
#include <math.h>

#define BB 2
#define SS 2048
#define DD 1024
#define HH 16
#define HKV 4
#define HDIM 64
#define SDIM 16

// ---------------- scratch (device globals; no allocation) ----------------
__device__ float    g_qlin[BB*SS*DD];
__device__ float    g_klin[BB*SS*HKV*HDIM];
__device__ float    g_vlin[BB*SS*HKV*HDIM];
__device__ unsigned g_q   [BB*HH*SS*HDIM];
__device__ unsigned g_qsp [BB*HH*SS*SDIM];
__device__ unsigned g_k   [BB*HKV*SS*HDIM];
__device__ unsigned g_ksp [BB*HKV*SS*SDIM];
__device__ unsigned g_v   [BB*HKV*HDIM*SS];   // TRANSPOSED: [b,hkv,d,s]
__device__ float    g_att [BB*SS*DD];
__device__ float    g_cosT[SS*(HDIM/2)];
__device__ float    g_sinT[SS*(HDIM/2)];
__device__ unsigned g_xc  [BB*SS*DD];
__device__ unsigned g_wqc [DD*DD];
__device__ unsigned g_wkc [HKV*HDIM*DD];
__device__ unsigned g_wvc [HKV*HDIM*DD];
__device__ unsigned g_woc [DD*DD];

// ---------------- common helpers ----------------
__device__ __forceinline__ unsigned f2tf32(float f) {
    unsigned r;
    asm("cvt.rna.tf32.f32 %0, %1;" : "=r"(r) : "f"(f));
    return r;
}
__device__ __forceinline__ float ex2f(float x) {
    float r;
    asm("ex2.approx.f32 %0, %1;" : "=f"(r) : "f"(x));
    return r;
}
__device__ __forceinline__ float rcpf(float x) {
    float r;
    asm("rcp.approx.f32 %0, %1;" : "=f"(r) : "f"(x));
    return r;
}
__device__ __forceinline__ float tanhf_a(float x) {
    float r;
    asm("tanh.approx.f32 %0, %1;" : "=f"(r) : "f"(x));
    return r;
}

__device__ __forceinline__ void mma_tf32(float& d0, float& d1, float& d2, float& d3,
                                         unsigned a0, unsigned a1, unsigned a2, unsigned a3,
                                         unsigned b0, unsigned b1) {
    asm volatile(
        "mma.sync.aligned.m16n8k8.row.col.f32.tf32.tf32.f32 "
        "{%0,%1,%2,%3},{%4,%5,%6,%7},{%8,%9},{%0,%1,%2,%3};"
        : "+f"(d0), "+f"(d1), "+f"(d2), "+f"(d3)
        : "r"(a0), "r"(a1), "r"(a2), "r"(a3), "r"(b0), "r"(b1));
}

__device__ __forceinline__ unsigned smem_u32(const void* p) {
    return (unsigned)__cvta_generic_to_shared(p);
}
__device__ __forceinline__ void cp16(unsigned dst, const void* src) {
    asm volatile("cp.async.cg.shared.global [%0], [%1], 16;" :: "r"(dst), "l"(src));
}
__device__ __forceinline__ uint4 ldsm4(unsigned addr) {
    uint4 r;
    asm volatile("ldmatrix.sync.aligned.m8n8.x4.shared.b16 {%0,%1,%2,%3}, [%4];"
                 : "=r"(r.x), "=r"(r.y), "=r"(r.z), "=r"(r.w) : "r"(addr));
    return r;
}

// ---------------- fused prologue: rope table + all tf32 conversions ----------------
#define PREP_BLOCKS 6912

__device__ __forceinline__ void cvt_seg(const float* __restrict__ in,
                                        unsigned* __restrict__ out, int blk) {
    int i = blk*256 + threadIdx.x;
    float4 f = ((const float4*)in)[i];
    uint4 u;
    u.x = f2tf32(f.x); u.y = f2tf32(f.y); u.z = f2tf32(f.z); u.w = f2tf32(f.w);
    ((uint4*)out)[i] = u;
}

__global__ void prep_kernel(const float* __restrict__ x,
                            const float* __restrict__ Wq,
                            const float* __restrict__ Wk,
                            const float* __restrict__ Wv,
                            const float* __restrict__ Wo)
{
    int bx = blockIdx.x;
    if (bx < 4096)      { cvt_seg(x,  g_xc,  bx); }
    else if (bx < 5120) { cvt_seg(Wq, g_wqc, bx - 4096); }
    else if (bx < 5376) { cvt_seg(Wk, g_wkc, bx - 5120); }
    else if (bx < 5632) { cvt_seg(Wv, g_wvc, bx - 5376); }
    else if (bx < 6656) { cvt_seg(Wo, g_woc, bx - 5632); }
    else {
        int idx = (bx - 6656)*256 + threadIdx.x;
        int s = idx / (HDIM/2), i = idx % (HDIM/2);
        float thf = (float)pow(10000.0, -(double)i / (double)(HDIM/2));
        float ff  = (float)s * thf;
        g_cosT[idx] = (float)cos((double)ff);
        g_sinT[idx] = (float)sin((double)ff);
    }
}

// ================= cp.async + ldmatrix TF32 GEMM =================
#define TBM 128
#define TBN 128
#define TBK 16
#define PADK 20
#define STG 3
#define GSMEM (STG*(TBM+TBN)*PADK*4)

__global__ void __launch_bounds__(256) gemm3(
    const unsigned* __restrict__ A,
    const unsigned* __restrict__ W0, float* __restrict__ C0, int nx0, int N0,
    const unsigned* __restrict__ W1, float* __restrict__ C1, int nx1, int N1,
    const unsigned* __restrict__ W2, float* __restrict__ C2, int nx2, int N2,
    const float* __restrict__ bias, int K)
{
    extern __shared__ unsigned sh[];
    unsigned* Asm = sh;
    unsigned* Bsm = sh + STG*TBM*PADK;

    const int tid = threadIdx.x;
    const int w = tid >> 5, lane = tid & 31;
    const int gid = lane >> 2, t4 = lane & 3;
    const int wm = w & 1, wn = w >> 1;
    const int row0 = blockIdx.y*TBM;

    const unsigned* Wp; float* Cp; int N, cb;
    int bx = blockIdx.x;
    if (bx < nx0)            { Wp = W0; Cp = C0; N = N0; cb = bx; }
    else if (bx < nx0 + nx1) { Wp = W1; Cp = C1; N = N1; cb = bx - nx0; }
    else                     { Wp = W2; Cp = C2; N = N2; cb = bx - nx0 - nx1; }
    const int col0 = cb*TBN;

    const unsigned* Aptr = A  + (size_t)row0*K;
    const unsigned* Wptr = Wp + (size_t)col0*K;

    const int r0c = tid >> 2, r1c = r0c + 64;
    const int cc  = (tid & 3) << 2;

    const unsigned asA = smem_u32(Asm);
    const unsigned asB = smem_u32(Bsm);

    int aoff[4], boff[2];
    #pragma unroll
    for (int mt = 0; mt < 4; mt++)
        aoff[mt] = (wm*64 + mt*16 + (lane & 15))*PADK + ((lane >> 4) << 2);
    #pragma unroll
    for (int np = 0; np < 2; np++)
        boff[np] = (wn*32 + np*16 + (lane & 15))*PADK + ((lane >> 4) << 2);

    #pragma unroll
    for (int s = 0; s < STG-1; s++) {
        int k0 = s*TBK;
        cp16(asA + (s*(TBM*PADK) + r0c*PADK + cc)*4, Aptr + (size_t)r0c*K + k0 + cc);
        cp16(asA + (s*(TBM*PADK) + r1c*PADK + cc)*4, Aptr + (size_t)r1c*K + k0 + cc);
        cp16(asB + (s*(TBN*PADK) + r0c*PADK + cc)*4, Wptr + (size_t)r0c*K + k0 + cc);
        cp16(asB + (s*(TBN*PADK) + r1c*PADK + cc)*4, Wptr + (size_t)r1c*K + k0 + cc);
        asm volatile("cp.async.commit_group;");
    }

    float acc[4][4][4];
    #pragma unroll
    for (int mt = 0; mt < 4; mt++)
        #pragma unroll
        for (int nt = 0; nt < 4; nt++)
            #pragma unroll
            for (int j = 0; j < 4; j++) acc[mt][nt][j] = 0.f;

    const int T = K / TBK;
    int st = 0, si = STG - 1;
    for (int t = 0; t < T; t++) {
        asm volatile("cp.async.wait_group 1;" ::: "memory");
        __syncthreads();

        if (t + STG - 1 < T) {
            int k0 = (t + STG - 1)*TBK;
            cp16(asA + (si*(TBM*PADK) + r0c*PADK + cc)*4, Aptr + (size_t)r0c*K + k0 + cc);
            cp16(asA + (si*(TBM*PADK) + r1c*PADK + cc)*4, Aptr + (size_t)r1c*K + k0 + cc);
            cp16(asB + (si*(TBN*PADK) + r0c*PADK + cc)*4, Wptr + (size_t)r0c*K + k0 + cc);
            cp16(asB + (si*(TBN*PADK) + r1c*PADK + cc)*4, Wptr + (size_t)r1c*K + k0 + cc);
        }
        asm volatile("cp.async.commit_group;");

        const unsigned aStg = asA + (st*(TBM*PADK))*4;
        const unsigned bStg = asB + (st*(TBN*PADK))*4;
        #pragma unroll
        for (int kk = 0; kk < TBK; kk += 8) {
            uint4 av[4], bv[2];
            #pragma unroll
            for (int mt = 0; mt < 4; mt++) av[mt] = ldsm4(aStg + (aoff[mt] + kk)*4);
            #pragma unroll
            for (int np = 0; np < 2; np++) bv[np] = ldsm4(bStg + (boff[np] + kk)*4);
            #pragma unroll
            for (int np = 0; np < 2; np++) {
                #pragma unroll
                for (int mt = 0; mt < 4; mt++) {
                    mma_tf32(acc[mt][2*np  ][0], acc[mt][2*np  ][1], acc[mt][2*np  ][2], acc[mt][2*np  ][3],
                             av[mt].x, av[mt].y, av[mt].z, av[mt].w, bv[np].x, bv[np].z);
                    mma_tf32(acc[mt][2*np+1][0], acc[mt][2*np+1][1], acc[mt][2*np+1][2], acc[mt][2*np+1][3],
                             av[mt].x, av[mt].y, av[mt].z, av[mt].w, bv[np].y, bv[np].w);
                }
            }
        }
        st = (st + 1 == STG) ? 0 : st + 1;
        si = (si + 1 == STG) ? 0 : si + 1;
    }

    #pragma unroll
    for (int mt = 0; mt < 4; mt++) {
        int r = row0 + wm*64 + mt*16 + gid;
        #pragma unroll
        for (int nt = 0; nt < 4; nt++) {
            int c = col0 + wn*32 + nt*8 + 2*t4;
            float bv0 = bias ? bias[c]   : 0.f;
            float bv1 = bias ? bias[c+1] : 0.f;
            *(float2*)&Cp[(size_t)r*N + c]     = make_float2(acc[mt][nt][0]+bv0, acc[mt][nt][1]+bv1);
            *(float2*)&Cp[(size_t)(r+8)*N + c] = make_float2(acc[mt][nt][2]+bv0, acc[mt][nt][3]+bv1);
        }
    }
}

// ---------------- fused RoPE + sparsity projection ----------------
__global__ void rope_sp_all(const float* __restrict__ Ws,
                            const float* __restrict__ bs)
{
    __shared__ float WsS[SDIM*HDIM];
    __shared__ float bsS[SDIM];
    for (int i = threadIdx.x; i < SDIM*HDIM; i += blockDim.x) WsS[i] = Ws[i];
    if (threadIdx.x < SDIM) bsS[threadIdx.x] = bs[threadIdx.x];
    __syncthreads();

    const int NQ = BB*SS*HH;
    int gidx = blockIdx.x*blockDim.x + threadIdx.x;

    const float* lin; unsigned *obuf, *spbuf;
    bool doV = false;
    int b, s, h, NH;
    if (gidx < NQ) {
        NH = HH;
        h = gidx % NH; s = (gidx / NH) % SS; b = gidx / (NH*SS);
        lin = g_qlin; obuf = g_q; spbuf = g_qsp;
    } else {
        int idx = gidx - NQ;
        if (idx >= BB*SS*HKV) return;
        NH = HKV;
        s = idx % SS; h = (idx / SS) % HKV; b = idx / (SS*HKV);
        lin = g_klin; obuf = g_k; spbuf = g_ksp;
        doV = true;
    }

    const float4* src = (const float4*)(lin + ((size_t)(b*SS + s)*NH + h)*HDIM);
    float v[HDIM];
    #pragma unroll
    for (int t = 0; t < HDIM/4; t++) ((float4*)v)[t] = src[t];

    #pragma unroll
    for (int i = 0; i < HDIM/2; i++) {
        float c  = g_cosT[s*(HDIM/2)+i];
        float sn = g_sinT[s*(HDIM/2)+i];
        float a  = v[i], bpart = v[i+HDIM/2];
        v[i]        = a*c - bpart*sn;
        v[i+HDIM/2] = bpart*c + a*sn;
    }

    unsigned* dst = obuf + (((size_t)b*NH + h)*SS + s)*HDIM;
    #pragma unroll
    for (int d = 0; d < HDIM; d += 4) {
        uint4 u;
        u.x = f2tf32(v[d]);   u.y = f2tf32(v[d+1]);
        u.z = f2tf32(v[d+2]); u.w = f2tf32(v[d+3]);
        *(uint4*)&dst[d] = u;
    }

    unsigned* spd = spbuf + (((size_t)b*NH + h)*SS + s)*SDIM;
    #pragma unroll
    for (int j = 0; j < SDIM; j++) {
        float acc = bsS[j];
        #pragma unroll
        for (int d = 0; d < HDIM; d++) acc += WsS[j*HDIM + d] * v[d];
        spd[j] = f2tf32(acc);
    }

    if (doV) {
        const float* vsrc = g_vlin + ((size_t)(b*SS + s)*NH + h)*HDIM;
        unsigned* vbase = g_v + ((size_t)(b*HKV + h)*HDIM)*SS + s;
        #pragma unroll
        for (int d = 0; d < HDIM; d++)
            vbase[(size_t)d*SS] = f2tf32(vsrc[d]);
    }
}

// ================= TF32 attention: no-max softmax (bounded logits), deferred l-reduce =================
#define AQT 128
#define AKT 64
#define KSTR 68
#define VTST 68
#define SSTR 20
#define KBUF (AKT*KSTR)
#define VBUF (AKT*VTST)
#define SBUF (AKT*SSTR)
#define ABUF (KBUF+VBUF+SBUF)
#define ASMEM (2*ABUF*4)

#define C_QK 0.1803368801f    // 0.125 * log2(e)

__global__ void __launch_bounds__(256, 2) attn_mma_kernel()
{
    extern __shared__ unsigned ash[];

    const int b = blockIdx.z, h = blockIdx.y;
    const int hkv = h >> 2;
    const int q0 = (gridDim.x - 1 - blockIdx.x) * AQT;
    const int tid = threadIdx.x;
    const int w = tid >> 5, lane = tid & 31;
    const int gid = lane >> 2, t4 = lane & 3;

    const int q0w = q0 + w*16;
    const int qr0 = q0w + gid;
    const int qr1 = qr0 + 8;

    const unsigned* qbase = g_q   + ((size_t)b*HH  + h  )*SS*HDIM;
    const unsigned* qspb  = g_qsp + ((size_t)b*HH  + h  )*SS*SDIM;
    const unsigned* kptr  = g_k   + ((size_t)b*HKV + hkv)*SS*HDIM;
    const unsigned* kspp  = g_ksp + ((size_t)b*HKV + hkv)*SS*SDIM;
    const unsigned* vtp   = g_v   + ((size_t)b*HKV + hkv)*HDIM*SS;

    const unsigned shbase = smem_u32(ash);

    const int lRow = ((lane >> 4) << 3) | (lane & 7);
    const int lCol = ((lane >> 3) & 1) << 2;

    unsigned qa[8][4], qsa[2][4];
    #pragma unroll
    for (int kt = 0; kt < 8; kt++) {
        qa[kt][0] = qbase[(size_t)qr0*HDIM + kt*8 + t4];
        qa[kt][1] = qbase[(size_t)qr1*HDIM + kt*8 + t4];
        qa[kt][2] = qbase[(size_t)qr0*HDIM + kt*8 + t4 + 4];
        qa[kt][3] = qbase[(size_t)qr1*HDIM + kt*8 + t4 + 4];
    }
    #pragma unroll
    for (int kt = 0; kt < 2; kt++) {
        qsa[kt][0] = qspb[(size_t)qr0*SDIM + kt*8 + t4];
        qsa[kt][1] = qspb[(size_t)qr1*SDIM + kt*8 + t4];
        qsa[kt][2] = qspb[(size_t)qr0*SDIM + kt*8 + t4 + 4];
        qsa[kt][3] = qspb[(size_t)qr1*SDIM + kt*8 + t4 + 4];
    }

    // lane-partial softmax denominators (reduced across quad in epilogue)
    float l0 = 0.f, l1 = 0.f;
    float O[8][4];
    #pragma unroll
    for (int dn = 0; dn < 8; dn++)
        #pragma unroll
        for (int j = 0; j < 4; j++) O[dn][j] = 0.f;

    const int srcA = (lane & ~3) | (t4 >> 1);
    const int srcB = srcA + 2;
    const bool odd = (t4 & 1);

    auto issue_tile = [&](int kb, int buf) {
        unsigned base = shbase + buf*ABUF*4;
        #pragma unroll
        for (int c = 0; c < 4; c++) {
            int i = tid + c*256;
            int r = i >> 4, q4 = (i & 15) << 2;
            cp16(base + (r*KSTR + q4)*4,          kptr + (size_t)(kb+r)*HDIM + q4);
            cp16(base + (KBUF + r*VTST + q4)*4,   vtp  + (size_t)r*SS + kb + q4);
        }
        {
            int key = tid >> 2, j4 = (tid & 3) << 2;
            cp16(base + (KBUF + VBUF + key*SSTR + j4)*4, kspp + (size_t)(kb+key)*SDIM + j4);
        }
    };

    const int nTiles = (q0 + AQT) / AKT;
    issue_tile(0, 0);
    asm volatile("cp.async.commit_group;");

    for (int t = 0; t < nTiles; t++) {
        const int kb = t*AKT;
        const int buf = t & 1;
        __syncthreads();
        if (t + 1 < nTiles) issue_tile(kb + AKT, buf ^ 1);
        asm volatile("cp.async.commit_group;");
        asm volatile("cp.async.wait_group 1;" ::: "memory");
        __syncthreads();

        if (kb > q0w + 15) continue;

        const unsigned kBase  = shbase + buf*ABUF*4;
        const unsigned vtBase = kBase + KBUF*4;
        const unsigned spBase = kBase + (KBUF+VBUF)*4;

        float S[8][4];
        #pragma unroll
        for (int nt = 0; nt < 8; nt++)
            #pragma unroll
            for (int j = 0; j < 4; j++) S[nt][j] = 0.f;

        // ---- S = Q K^T ----
        #pragma unroll
        for (int kt = 0; kt < 8; kt++) {
            #pragma unroll
            for (int g2 = 0; g2 < 4; g2++) {
                uint4 bb = ldsm4(kBase + (((g2*16 + lRow)*KSTR) + kt*8 + lCol)*4);
                mma_tf32(S[2*g2  ][0], S[2*g2  ][1], S[2*g2  ][2], S[2*g2  ][3],
                         qa[kt][0], qa[kt][1], qa[kt][2], qa[kt][3], bb.x, bb.y);
                mma_tf32(S[2*g2+1][0], S[2*g2+1][1], S[2*g2+1][2], S[2*g2+1][3],
                         qa[kt][0], qa[kt][1], qa[kt][2], qa[kt][3], bb.z, bb.w);
            }
        }

        // ---- gate (tanh) + causal mask + UNNORMALIZED exp (logits bounded) ----
        #pragma unroll
        for (int g2 = 0; g2 < 4; g2++) {
            float sp0[4] = {0.f,0.f,0.f,0.f}, sp1[4] = {0.f,0.f,0.f,0.f};
            uint4 b0 = ldsm4(spBase + (((g2*16 + lRow)*SSTR) + 0 + lCol)*4);
            uint4 b1 = ldsm4(spBase + (((g2*16 + lRow)*SSTR) + 8 + lCol)*4);
            mma_tf32(sp0[0], sp0[1], sp0[2], sp0[3],
                     qsa[0][0], qsa[0][1], qsa[0][2], qsa[0][3], b0.x, b0.y);
            mma_tf32(sp0[0], sp0[1], sp0[2], sp0[3],
                     qsa[1][0], qsa[1][1], qsa[1][2], qsa[1][3], b1.x, b1.y);
            mma_tf32(sp1[0], sp1[1], sp1[2], sp1[3],
                     qsa[0][0], qsa[0][1], qsa[0][2], qsa[0][3], b0.z, b0.w);
            mma_tf32(sp1[0], sp1[1], sp1[2], sp1[3],
                     qsa[1][0], qsa[1][1], qsa[1][2], qsa[1][3], b1.z, b1.w);

            #pragma unroll
            for (int j = 0; j < 4; j++) {
                {
                    int key = kb + (2*g2)*8 + 2*t4 + (j & 1);
                    int row = (j >= 2) ? qr1 : qr0;
                    float gf = fmaf(0.5f, tanhf_a(sp0[j] * 0.125f), 0.5f); // sigmoid(sp/4)
                    float lg = S[2*g2][j] * C_QK * gf;
                    float p  = (key > row) ? 0.f : ex2f(lg);
                    S[2*g2][j] = p;
                    if (j >= 2) l1 += p; else l0 += p;
                }
                {
                    int key = kb + (2*g2+1)*8 + 2*t4 + (j & 1);
                    int row = (j >= 2) ? qr1 : qr0;
                    float gf = fmaf(0.5f, tanhf_a(sp1[j] * 0.125f), 0.5f);
                    float lg = S[2*g2+1][j] * C_QK * gf;
                    float p  = (key > row) ? 0.f : ex2f(lg);
                    S[2*g2+1][j] = p;
                    if (j >= 2) l1 += p; else l0 += p;
                }
            }
        }

        // ---- O += P V (no rescale needed — unnormalized accumulation) ----
        #pragma unroll
        for (int kt = 0; kt < 8; kt++) {
            float e, o;
            e = __shfl_sync(0xffffffffu, S[kt][0], srcA);
            o = __shfl_sync(0xffffffffu, S[kt][1], srcA);
            unsigned a0 = f2tf32(odd ? o : e);
            e = __shfl_sync(0xffffffffu, S[kt][2], srcA);
            o = __shfl_sync(0xffffffffu, S[kt][3], srcA);
            unsigned a1 = f2tf32(odd ? o : e);
            e = __shfl_sync(0xffffffffu, S[kt][0], srcB);
            o = __shfl_sync(0xffffffffu, S[kt][1], srcB);
            unsigned a2 = f2tf32(odd ? o : e);
            e = __shfl_sync(0xffffffffu, S[kt][2], srcB);
            o = __shfl_sync(0xffffffffu, S[kt][3], srcB);
            unsigned a3 = f2tf32(odd ? o : e);

            #pragma unroll
            for (int d2 = 0; d2 < 4; d2++) {
                uint4 bb = ldsm4(vtBase + (((d2*16 + lRow)*VTST) + kt*8 + lCol)*4);
                mma_tf32(O[2*d2  ][0], O[2*d2  ][1], O[2*d2  ][2], O[2*d2  ][3],
                         a0, a1, a2, a3, bb.x, bb.y);
                mma_tf32(O[2*d2+1][0], O[2*d2+1][1], O[2*d2+1][2], O[2*d2+1][3],
                         a0, a1, a2, a3, bb.z, bb.w);
            }
        }
    }

    // epilogue: reduce l across quad lanes once, then normalize
    #pragma unroll
    for (int off = 1; off < 4; off <<= 1) {
        l0 += __shfl_xor_sync(0xffffffffu, l0, off);
        l1 += __shfl_xor_sync(0xffffffffu, l1, off);
    }
    float inv0 = rcpf(l0), inv1 = rcpf(l1);
    #pragma unroll
    for (int dn = 0; dn < 8; dn++) {
        int col = h*HDIM + dn*8 + 2*t4;
        float2 r0 = make_float2(__uint_as_float(f2tf32(O[dn][0]*inv0)),
                                __uint_as_float(f2tf32(O[dn][1]*inv0)));
        float2 r1 = make_float2(__uint_as_float(f2tf32(O[dn][2]*inv1)),
                                __uint_as_float(f2tf32(O[dn][3]*inv1)));
        *(float2*)&g_att[((size_t)b*SS + qr0)*DD + col] = r0;
        *(float2*)&g_att[((size_t)b*SS + qr1)*DD + col] = r1;
    }
}

// ---------------- launch ----------------
extern "C" void kernel_launch(void* const* d_in, const int* in_sizes, int n_in,
                              void* d_out, int out_size)
{
    (void)in_sizes; (void)n_in; (void)out_size;
    const float* x  = (const float*)d_in[0];
    const float* Wq = (const float*)d_in[1];
    const float* Wk = (const float*)d_in[2];
    const float* Wv = (const float*)d_in[3];
    const float* Wo = (const float*)d_in[4];
    const float* bo = (const float*)d_in[5];
    const float* Ws = (const float*)d_in[6];
    const float* bs = (const float*)d_in[7];
    float* out = (float*)d_out;

    float *qlin, *klin, *vlin, *att;
    unsigned *xc, *wqc, *wkc, *wvc, *woc;
    cudaGetSymbolAddress((void**)&qlin, g_qlin);
    cudaGetSymbolAddress((void**)&klin, g_klin);
    cudaGetSymbolAddress((void**)&vlin, g_vlin);
    cudaGetSymbolAddress((void**)&att,  g_att);
    cudaGetSymbolAddress((void**)&xc,   g_xc);
    cudaGetSymbolAddress((void**)&wqc,  g_wqc);
    cudaGetSymbolAddress((void**)&wkc,  g_wkc);
    cudaGetSymbolAddress((void**)&wvc,  g_wvc);
    cudaGetSymbolAddress((void**)&woc,  g_woc);

    const int M = BB*SS;   // 4096

    static bool attr_set = false;
    if (!attr_set) {
        cudaFuncSetAttribute(gemm3, cudaFuncAttributeMaxDynamicSharedMemorySize, GSMEM);
        cudaFuncSetAttribute(attn_mma_kernel, cudaFuncAttributeMaxDynamicSharedMemorySize, ASMEM);
        attr_set = true;
    }

    prep_kernel<<<PREP_BLOCKS, 256>>>(x, Wq, Wk, Wv, Wo);

    gemm3<<<dim3(12, M/TBM), 256, GSMEM>>>(xc,
                                    wqc, qlin, 8, DD,
                                    wkc, klin, 2, HKV*HDIM,
                                    wvc, vlin, 2, HKV*HDIM,
                                    nullptr, DD);

    rope_sp_all<<<(BB*SS*(HH+HKV) + 255)/256, 256>>>(Ws, bs);

    attn_mma_kernel<<<dim3(SS/AQT, HH, BB), 256, ASMEM>>>();

    gemm3<<<dim3(8, M/TBM), 256, GSMEM>>>((const unsigned*)att,
                                    woc, out, 8, DD,
                                    nullptr, nullptr, 0, 0,
                                    nullptr, nullptr, 0, 0,
                                    bo, DD);
}

// round 13
// speedup vs baseline: 1.1984x; 1.1984x over previous
#include <cuda_runtime.h>
#include <cuda_bf16.h>
#include <cuda_fp16.h>
#include <math.h>

#define BB 2
#define SS 2048
#define DD 1024
#define HH 16
#define HKV 4
#define HDIM 64
#define SDIM 16

// ---------------- scratch (device globals; no allocation) ----------------
__device__ float    g_qlin[BB*SS*DD];
__device__ float    g_klin[BB*SS*HKV*HDIM];
__device__ float    g_vlin[BB*SS*HKV*HDIM];
// fp16 (half2-packed) attention operands
__device__ unsigned g_qh [BB*HH*SS*HDIM/2];
__device__ unsigned g_qsph[BB*HH*SS*SDIM/2];
__device__ unsigned g_kh [BB*HKV*SS*HDIM/2];
__device__ unsigned g_ksph[BB*HKV*SS*SDIM/2];
__device__ unsigned g_vh [BB*HKV*SS*HDIM/2];   // natural [b,hkv,s,d]
__device__ float    g_att [BB*SS*DD];
__device__ float    g_cosT[SS*(HDIM/2)];
__device__ float    g_sinT[SS*(HDIM/2)];
__device__ unsigned g_xc  [BB*SS*DD];
__device__ unsigned g_wqc [DD*DD];
__device__ unsigned g_wkc [HKV*HDIM*DD];
__device__ unsigned g_wvc [HKV*HDIM*DD];
__device__ unsigned g_woc [DD*DD];

// ---------------- common helpers ----------------
__device__ __forceinline__ unsigned f2tf32(float f) {
    unsigned r;
    asm("cvt.rna.tf32.f32 %0, %1;" : "=r"(r) : "f"(f));
    return r;
}
__device__ __forceinline__ float ex2f(float x) {
    float r;
    asm("ex2.approx.f32 %0, %1;" : "=f"(r) : "f"(x));
    return r;
}
__device__ __forceinline__ float rcpf(float x) {
    float r;
    asm("rcp.approx.f32 %0, %1;" : "=f"(r) : "f"(x));
    return r;
}
__device__ __forceinline__ float tanhf_a(float x) {
    float r;
    asm("tanh.approx.f32 %0, %1;" : "=f"(r) : "f"(x));
    return r;
}
// pack {lo=a, hi=b} into half2 bits
__device__ __forceinline__ unsigned packh2(float a, float b) {
    unsigned r;
    asm("cvt.rn.f16x2.f32 %0, %1, %2;" : "=r"(r) : "f"(b), "f"(a));
    return r;
}

__device__ __forceinline__ void mma_tf32(float& d0, float& d1, float& d2, float& d3,
                                         unsigned a0, unsigned a1, unsigned a2, unsigned a3,
                                         unsigned b0, unsigned b1) {
    asm volatile(
        "mma.sync.aligned.m16n8k8.row.col.f32.tf32.tf32.f32 "
        "{%0,%1,%2,%3},{%4,%5,%6,%7},{%8,%9},{%0,%1,%2,%3};"
        : "+f"(d0), "+f"(d1), "+f"(d2), "+f"(d3)
        : "r"(a0), "r"(a1), "r"(a2), "r"(a3), "r"(b0), "r"(b1));
}
__device__ __forceinline__ void mma_f16(float& d0, float& d1, float& d2, float& d3,
                                        unsigned a0, unsigned a1, unsigned a2, unsigned a3,
                                        unsigned b0, unsigned b1) {
    asm volatile(
        "mma.sync.aligned.m16n8k16.row.col.f32.f16.f16.f32 "
        "{%0,%1,%2,%3},{%4,%5,%6,%7},{%8,%9},{%0,%1,%2,%3};"
        : "+f"(d0), "+f"(d1), "+f"(d2), "+f"(d3)
        : "r"(a0), "r"(a1), "r"(a2), "r"(a3), "r"(b0), "r"(b1));
}

__device__ __forceinline__ unsigned smem_u32(const void* p) {
    return (unsigned)__cvta_generic_to_shared(p);
}
__device__ __forceinline__ void cp16(unsigned dst, const void* src) {
    asm volatile("cp.async.cg.shared.global [%0], [%1], 16;" :: "r"(dst), "l"(src));
}
__device__ __forceinline__ uint4 ldsm4(unsigned addr) {
    uint4 r;
    asm volatile("ldmatrix.sync.aligned.m8n8.x4.shared.b16 {%0,%1,%2,%3}, [%4];"
                 : "=r"(r.x), "=r"(r.y), "=r"(r.z), "=r"(r.w) : "r"(addr));
    return r;
}
__device__ __forceinline__ uint4 ldsm4t(unsigned addr) {
    uint4 r;
    asm volatile("ldmatrix.sync.aligned.m8n8.x4.trans.shared.b16 {%0,%1,%2,%3}, [%4];"
                 : "=r"(r.x), "=r"(r.y), "=r"(r.z), "=r"(r.w) : "r"(addr));
    return r;
}

// ---------------- fused prologue: rope table + all tf32 conversions ----------------
#define PREP_BLOCKS 6912

__device__ __forceinline__ void cvt_seg(const float* __restrict__ in,
                                        unsigned* __restrict__ out, int blk) {
    int i = blk*256 + threadIdx.x;
    float4 f = ((const float4*)in)[i];
    uint4 u;
    u.x = f2tf32(f.x); u.y = f2tf32(f.y); u.z = f2tf32(f.z); u.w = f2tf32(f.w);
    ((uint4*)out)[i] = u;
}

__global__ void prep_kernel(const float* __restrict__ x,
                            const float* __restrict__ Wq,
                            const float* __restrict__ Wk,
                            const float* __restrict__ Wv,
                            const float* __restrict__ Wo)
{
    int bx = blockIdx.x;
    if (bx < 4096)      { cvt_seg(x,  g_xc,  bx); }
    else if (bx < 5120) { cvt_seg(Wq, g_wqc, bx - 4096); }
    else if (bx < 5376) { cvt_seg(Wk, g_wkc, bx - 5120); }
    else if (bx < 5632) { cvt_seg(Wv, g_wvc, bx - 5376); }
    else if (bx < 6656) { cvt_seg(Wo, g_woc, bx - 5632); }
    else {
        int idx = (bx - 6656)*256 + threadIdx.x;
        int s = idx / (HDIM/2), i = idx % (HDIM/2);
        float thf = (float)pow(10000.0, -(double)i / (double)(HDIM/2));
        float ff  = (float)s * thf;
        g_cosT[idx] = (float)cos((double)ff);
        g_sinT[idx] = (float)sin((double)ff);
    }
}

// ================= cp.async + ldmatrix TF32 GEMM (unchanged) =================
#define TBM 128
#define TBN 128
#define TBK 16
#define PADK 20
#define STG 3
#define GSMEM (STG*(TBM+TBN)*PADK*4)

__global__ void __launch_bounds__(256) gemm3(
    const unsigned* __restrict__ A,
    const unsigned* __restrict__ W0, float* __restrict__ C0, int nx0, int N0,
    const unsigned* __restrict__ W1, float* __restrict__ C1, int nx1, int N1,
    const unsigned* __restrict__ W2, float* __restrict__ C2, int nx2, int N2,
    const float* __restrict__ bias, int K)
{
    extern __shared__ unsigned sh[];
    unsigned* Asm = sh;
    unsigned* Bsm = sh + STG*TBM*PADK;

    const int tid = threadIdx.x;
    const int w = tid >> 5, lane = tid & 31;
    const int gid = lane >> 2, t4 = lane & 3;
    const int wm = w & 1, wn = w >> 1;
    const int row0 = blockIdx.y*TBM;

    const unsigned* Wp; float* Cp; int N, cb;
    int bx = blockIdx.x;
    if (bx < nx0)            { Wp = W0; Cp = C0; N = N0; cb = bx; }
    else if (bx < nx0 + nx1) { Wp = W1; Cp = C1; N = N1; cb = bx - nx0; }
    else                     { Wp = W2; Cp = C2; N = N2; cb = bx - nx0 - nx1; }
    const int col0 = cb*TBN;

    const unsigned* Aptr = A  + (size_t)row0*K;
    const unsigned* Wptr = Wp + (size_t)col0*K;

    const int r0c = tid >> 2, r1c = r0c + 64;
    const int cc  = (tid & 3) << 2;

    const unsigned asA = smem_u32(Asm);
    const unsigned asB = smem_u32(Bsm);

    int aoff[4], boff[2];
    #pragma unroll
    for (int mt = 0; mt < 4; mt++)
        aoff[mt] = (wm*64 + mt*16 + (lane & 15))*PADK + ((lane >> 4) << 2);
    #pragma unroll
    for (int np = 0; np < 2; np++)
        boff[np] = (wn*32 + np*16 + (lane & 15))*PADK + ((lane >> 4) << 2);

    #pragma unroll
    for (int s = 0; s < STG-1; s++) {
        int k0 = s*TBK;
        cp16(asA + (s*(TBM*PADK) + r0c*PADK + cc)*4, Aptr + (size_t)r0c*K + k0 + cc);
        cp16(asA + (s*(TBM*PADK) + r1c*PADK + cc)*4, Aptr + (size_t)r1c*K + k0 + cc);
        cp16(asB + (s*(TBN*PADK) + r0c*PADK + cc)*4, Wptr + (size_t)r0c*K + k0 + cc);
        cp16(asB + (s*(TBN*PADK) + r1c*PADK + cc)*4, Wptr + (size_t)r1c*K + k0 + cc);
        asm volatile("cp.async.commit_group;");
    }

    float acc[4][4][4];
    #pragma unroll
    for (int mt = 0; mt < 4; mt++)
        #pragma unroll
        for (int nt = 0; nt < 4; nt++)
            #pragma unroll
            for (int j = 0; j < 4; j++) acc[mt][nt][j] = 0.f;

    const int T = K / TBK;
    int st = 0, si = STG - 1;
    for (int t = 0; t < T; t++) {
        asm volatile("cp.async.wait_group 1;" ::: "memory");
        __syncthreads();

        if (t + STG - 1 < T) {
            int k0 = (t + STG - 1)*TBK;
            cp16(asA + (si*(TBM*PADK) + r0c*PADK + cc)*4, Aptr + (size_t)r0c*K + k0 + cc);
            cp16(asA + (si*(TBM*PADK) + r1c*PADK + cc)*4, Aptr + (size_t)r1c*K + k0 + cc);
            cp16(asB + (si*(TBN*PADK) + r0c*PADK + cc)*4, Wptr + (size_t)r0c*K + k0 + cc);
            cp16(asB + (si*(TBN*PADK) + r1c*PADK + cc)*4, Wptr + (size_t)r1c*K + k0 + cc);
        }
        asm volatile("cp.async.commit_group;");

        const unsigned aStg = asA + (st*(TBM*PADK))*4;
        const unsigned bStg = asB + (st*(TBN*PADK))*4;
        #pragma unroll
        for (int kk = 0; kk < TBK; kk += 8) {
            uint4 av[4], bv[2];
            #pragma unroll
            for (int mt = 0; mt < 4; mt++) av[mt] = ldsm4(aStg + (aoff[mt] + kk)*4);
            #pragma unroll
            for (int np = 0; np < 2; np++) bv[np] = ldsm4(bStg + (boff[np] + kk)*4);
            #pragma unroll
            for (int np = 0; np < 2; np++) {
                #pragma unroll
                for (int mt = 0; mt < 4; mt++) {
                    mma_tf32(acc[mt][2*np  ][0], acc[mt][2*np  ][1], acc[mt][2*np  ][2], acc[mt][2*np  ][3],
                             av[mt].x, av[mt].y, av[mt].z, av[mt].w, bv[np].x, bv[np].z);
                    mma_tf32(acc[mt][2*np+1][0], acc[mt][2*np+1][1], acc[mt][2*np+1][2], acc[mt][2*np+1][3],
                             av[mt].x, av[mt].y, av[mt].z, av[mt].w, bv[np].y, bv[np].w);
                }
            }
        }
        st = (st + 1 == STG) ? 0 : st + 1;
        si = (si + 1 == STG) ? 0 : si + 1;
    }

    #pragma unroll
    for (int mt = 0; mt < 4; mt++) {
        int r = row0 + wm*64 + mt*16 + gid;
        #pragma unroll
        for (int nt = 0; nt < 4; nt++) {
            int c = col0 + wn*32 + nt*8 + 2*t4;
            float bv0 = bias ? bias[c]   : 0.f;
            float bv1 = bias ? bias[c+1] : 0.f;
            *(float2*)&Cp[(size_t)r*N + c]     = make_float2(acc[mt][nt][0]+bv0, acc[mt][nt][1]+bv1);
            *(float2*)&Cp[(size_t)(r+8)*N + c] = make_float2(acc[mt][nt][2]+bv0, acc[mt][nt][3]+bv1);
        }
    }
}

// ---------------- fused RoPE + sparsity projection -> fp16 outputs ----------------
__global__ void rope_sp_all(const float* __restrict__ Ws,
                            const float* __restrict__ bs)
{
    __shared__ float WsS[SDIM*HDIM];
    __shared__ float bsS[SDIM];
    for (int i = threadIdx.x; i < SDIM*HDIM; i += blockDim.x) WsS[i] = Ws[i];
    if (threadIdx.x < SDIM) bsS[threadIdx.x] = bs[threadIdx.x];
    __syncthreads();

    const int NQ = BB*SS*HH;
    int gidx = blockIdx.x*blockDim.x + threadIdx.x;

    const float* lin; unsigned *obuf, *spbuf;
    bool doV = false;
    int b, s, h, NH;
    if (gidx < NQ) {
        NH = HH;
        h = gidx % NH; s = (gidx / NH) % SS; b = gidx / (NH*SS);
        lin = g_qlin; obuf = g_qh; spbuf = g_qsph;
    } else {
        int idx = gidx - NQ;
        if (idx >= BB*SS*HKV) return;
        NH = HKV;
        s = idx % SS; h = (idx / SS) % HKV; b = idx / (SS*HKV);
        lin = g_klin; obuf = g_kh; spbuf = g_ksph;
        doV = true;
    }

    const float4* src = (const float4*)(lin + ((size_t)(b*SS + s)*NH + h)*HDIM);
    float v[HDIM];
    #pragma unroll
    for (int t = 0; t < HDIM/4; t++) ((float4*)v)[t] = src[t];

    #pragma unroll
    for (int i = 0; i < HDIM/2; i++) {
        float c  = g_cosT[s*(HDIM/2)+i];
        float sn = g_sinT[s*(HDIM/2)+i];
        float a  = v[i], bpart = v[i+HDIM/2];
        v[i]        = a*c - bpart*sn;
        v[i+HDIM/2] = bpart*c + a*sn;
    }

    unsigned hh[HDIM/2];
    #pragma unroll
    for (int d = 0; d < HDIM/2; d++) hh[d] = packh2(v[2*d], v[2*d+1]);
    unsigned* dst = obuf + (((size_t)b*NH + h)*SS + s)*(HDIM/2);
    #pragma unroll
    for (int t = 0; t < HDIM/8; t++) ((uint4*)dst)[t] = ((uint4*)hh)[t];

    float sp[SDIM];
    #pragma unroll
    for (int j = 0; j < SDIM; j++) {
        float acc = bsS[j];
        #pragma unroll
        for (int d = 0; d < HDIM; d++) acc += WsS[j*HDIM + d] * v[d];
        sp[j] = acc;
    }
    unsigned* spd = spbuf + (((size_t)b*NH + h)*SS + s)*(SDIM/2);
    #pragma unroll
    for (int j = 0; j < SDIM/2; j++) spd[j] = packh2(sp[2*j], sp[2*j+1]);

    if (doV) {
        const float* vsrc = g_vlin + ((size_t)(b*SS + s)*NH + h)*HDIM;
        unsigned vv[HDIM/2];
        #pragma unroll
        for (int d = 0; d < HDIM/2; d++) vv[d] = packh2(vsrc[2*d], vsrc[2*d+1]);
        unsigned* vdst = g_vh + (((size_t)b*HKV + h)*SS + s)*(HDIM/2);
        #pragma unroll
        for (int t = 0; t < HDIM/8; t++) ((uint4*)vdst)[t] = ((uint4*)vv)[t];
    }
}

// ================= FP16 m16n8k16 attention =================
#define AQT 128
#define AKT 64
#define KSTRB 144     // K/V smem row stride in BYTES (72 halves)
#define SSTRB 48      // Ksp row stride bytes (24 halves)
#define KBUFB (AKT*KSTRB)          // 9216
#define VBUFB (AKT*KSTRB)          // 9216
#define SBUFB (AKT*SSTRB)          // 3072
#define ABUFB (KBUFB+VBUFB+SBUFB)  // 21504
#define ASMEM (2*ABUFB)

#define C_QK 0.1803368801f    // 0.125 * log2(e)

__global__ void __launch_bounds__(256, 2) attn_mma_kernel()
{
    extern __shared__ unsigned ash[];

    const int b = blockIdx.z, h = blockIdx.y;
    const int hkv = h >> 2;
    const int q0 = (gridDim.x - 1 - blockIdx.x) * AQT;
    const int tid = threadIdx.x;
    const int w = tid >> 5, lane = tid & 31;
    const int gid = lane >> 2, t4 = lane & 3;

    const int q0w = q0 + w*16;
    const int qr0 = q0w + gid;
    const int qr1 = qr0 + 8;

    const unsigned* qh2  = g_qh  + ((size_t)b*HH  + h  )*SS*(HDIM/2);
    const unsigned* qsph = g_qsph+ ((size_t)b*HH  + h  )*SS*(SDIM/2);
    const unsigned* kh2  = g_kh  + ((size_t)b*HKV + hkv)*SS*(HDIM/2);
    const unsigned* ksph = g_ksph+ ((size_t)b*HKV + hkv)*SS*(SDIM/2);
    const unsigned* vh2  = g_vh  + ((size_t)b*HKV + hkv)*SS*(HDIM/2);

    const unsigned shbase = smem_u32(ash);

    // ldsm lane selectors
    const int kRow = ((lane >> 4) << 3) | (lane & 7);       // non-trans (K, Ksp)
    const int kCol = ((lane >> 3) & 1) << 3;                //   (halves)
    const int vRow = (((lane >> 3) & 1) << 3) | (lane & 7); // trans (V)
    const int vCol = (lane >> 4) << 3;                      //   (halves)

    // Q fragments: 4 k16 steps
    unsigned qa[4][4], qsa[4];
    #pragma unroll
    for (int kt = 0; kt < 4; kt++) {
        qa[kt][0] = qh2[(size_t)qr0*(HDIM/2) + kt*8 + t4];
        qa[kt][1] = qh2[(size_t)qr1*(HDIM/2) + kt*8 + t4];
        qa[kt][2] = qh2[(size_t)qr0*(HDIM/2) + kt*8 + t4 + 4];
        qa[kt][3] = qh2[(size_t)qr1*(HDIM/2) + kt*8 + t4 + 4];
    }
    qsa[0] = qsph[(size_t)qr0*(SDIM/2) + t4];
    qsa[1] = qsph[(size_t)qr1*(SDIM/2) + t4];
    qsa[2] = qsph[(size_t)qr0*(SDIM/2) + t4 + 4];
    qsa[3] = qsph[(size_t)qr1*(SDIM/2) + t4 + 4];

    float l0 = 0.f, l1 = 0.f;
    float O[8][4];
    #pragma unroll
    for (int dn = 0; dn < 8; dn++)
        #pragma unroll
        for (int j = 0; j < 4; j++) O[dn][j] = 0.f;

    auto issue_tile = [&](int kb, int buf) {
        unsigned base = shbase + buf*ABUFB;
        #pragma unroll
        for (int c = 0; c < 2; c++) {
            int i = tid + c*256;                 // 512 chunks
            int key = i >> 3, c8 = i & 7;
            cp16(base + key*KSTRB + c8*16,          kh2 + (size_t)(kb+key)*(HDIM/2) + c8*4);
            cp16(base + KBUFB + key*KSTRB + c8*16,  vh2 + (size_t)(kb+key)*(HDIM/2) + c8*4);
        }
        if (tid < 128) {
            int key = tid >> 1, c2 = tid & 1;
            cp16(base + KBUFB + VBUFB + key*SSTRB + c2*16,
                 ksph + (size_t)(kb+key)*(SDIM/2) + c2*4);
        }
    };

    const int nTiles = (q0 + AQT) / AKT;
    issue_tile(0, 0);
    asm volatile("cp.async.commit_group;");

    for (int t = 0; t < nTiles; t++) {
        const int kb = t*AKT;
        const int buf = t & 1;
        __syncthreads();
        if (t + 1 < nTiles) issue_tile(kb + AKT, buf ^ 1);
        asm volatile("cp.async.commit_group;");
        asm volatile("cp.async.wait_group 1;" ::: "memory");
        __syncthreads();

        if (kb > q0w + 15) continue;

        const unsigned kBase  = shbase + buf*ABUFB;
        const unsigned vBase  = kBase + KBUFB;
        const unsigned spBase = kBase + KBUFB + VBUFB;

        float S[8][4];
        #pragma unroll
        for (int nt = 0; nt < 8; nt++)
            #pragma unroll
            for (int j = 0; j < 4; j++) S[nt][j] = 0.f;

        // ---- S = Q K^T : 4 k16-steps x 4 key-pair-groups ----
        #pragma unroll
        for (int kt = 0; kt < 4; kt++) {
            #pragma unroll
            for (int g2 = 0; g2 < 4; g2++) {
                uint4 bb = ldsm4(kBase + (g2*16 + kRow)*KSTRB + (kt*16 + kCol)*2);
                mma_f16(S[2*g2  ][0], S[2*g2  ][1], S[2*g2  ][2], S[2*g2  ][3],
                        qa[kt][0], qa[kt][1], qa[kt][2], qa[kt][3], bb.x, bb.y);
                mma_f16(S[2*g2+1][0], S[2*g2+1][1], S[2*g2+1][2], S[2*g2+1][3],
                        qa[kt][0], qa[kt][1], qa[kt][2], qa[kt][3], bb.z, bb.w);
            }
        }

        // ---- gate (single k16 step) + causal mask + unnormalized exp ----
        #pragma unroll
        for (int g2 = 0; g2 < 4; g2++) {
            float sp0[4] = {0.f,0.f,0.f,0.f}, sp1[4] = {0.f,0.f,0.f,0.f};
            uint4 bb = ldsm4(spBase + (g2*16 + kRow)*SSTRB + kCol*2);
            mma_f16(sp0[0], sp0[1], sp0[2], sp0[3],
                    qsa[0], qsa[1], qsa[2], qsa[3], bb.x, bb.y);
            mma_f16(sp1[0], sp1[1], sp1[2], sp1[3],
                    qsa[0], qsa[1], qsa[2], qsa[3], bb.z, bb.w);

            #pragma unroll
            for (int j = 0; j < 4; j++) {
                {
                    int key = kb + (2*g2)*8 + 2*t4 + (j & 1);
                    int row = (j >= 2) ? qr1 : qr0;
                    float gf = fmaf(0.5f, tanhf_a(sp0[j] * 0.125f), 0.5f);
                    float p  = (key > row) ? 0.f : ex2f(S[2*g2][j] * C_QK * gf);
                    S[2*g2][j] = p;
                    if (j >= 2) l1 += p; else l0 += p;
                }
                {
                    int key = kb + (2*g2+1)*8 + 2*t4 + (j & 1);
                    int row = (j >= 2) ? qr1 : qr0;
                    float gf = fmaf(0.5f, tanhf_a(sp1[j] * 0.125f), 0.5f);
                    float p  = (key > row) ? 0.f : ex2f(S[2*g2+1][j] * C_QK * gf);
                    S[2*g2+1][j] = p;
                    if (j >= 2) l1 += p; else l0 += p;
                }
            }
        }

        // ---- O += P V : P C-fragments pack directly into A-fragments ----
        #pragma unroll
        for (int kt = 0; kt < 4; kt++) {
            unsigned a0 = packh2(S[2*kt  ][0], S[2*kt  ][1]);
            unsigned a1 = packh2(S[2*kt  ][2], S[2*kt  ][3]);
            unsigned a2 = packh2(S[2*kt+1][0], S[2*kt+1][1]);
            unsigned a3 = packh2(S[2*kt+1][2], S[2*kt+1][3]);

            #pragma unroll
            for (int dnp = 0; dnp < 4; dnp++) {
                uint4 bb = ldsm4t(vBase + (kt*16 + vRow)*KSTRB + (dnp*16 + vCol)*2);
                mma_f16(O[2*dnp  ][0], O[2*dnp  ][1], O[2*dnp  ][2], O[2*dnp  ][3],
                        a0, a1, a2, a3, bb.x, bb.y);
                mma_f16(O[2*dnp+1][0], O[2*dnp+1][1], O[2*dnp+1][2], O[2*dnp+1][3],
                        a0, a1, a2, a3, bb.z, bb.w);
            }
        }
    }

    // epilogue: reduce l across quad, normalize, store tf32 bits for O GEMM
    #pragma unroll
    for (int off = 1; off < 4; off <<= 1) {
        l0 += __shfl_xor_sync(0xffffffffu, l0, off);
        l1 += __shfl_xor_sync(0xffffffffu, l1, off);
    }
    float inv0 = rcpf(l0), inv1 = rcpf(l1);
    #pragma unroll
    for (int dn = 0; dn < 8; dn++) {
        int col = h*HDIM + dn*8 + 2*t4;
        float2 r0 = make_float2(__uint_as_float(f2tf32(O[dn][0]*inv0)),
                                __uint_as_float(f2tf32(O[dn][1]*inv0)));
        float2 r1 = make_float2(__uint_as_float(f2tf32(O[dn][2]*inv1)),
                                __uint_as_float(f2tf32(O[dn][3]*inv1)));
        *(float2*)&g_att[((size_t)b*SS + qr0)*DD + col] = r0;
        *(float2*)&g_att[((size_t)b*SS + qr1)*DD + col] = r1;
    }
}

// ---------------- launch ----------------
extern "C" void kernel_launch(void* const* d_in, const int* in_sizes, int n_in,
                              void* d_out, int out_size)
{
    (void)in_sizes; (void)n_in; (void)out_size;
    const float* x  = (const float*)d_in[0];
    const float* Wq = (const float*)d_in[1];
    const float* Wk = (const float*)d_in[2];
    const float* Wv = (const float*)d_in[3];
    const float* Wo = (const float*)d_in[4];
    const float* bo = (const float*)d_in[5];
    const float* Ws = (const float*)d_in[6];
    const float* bs = (const float*)d_in[7];
    float* out = (float*)d_out;

    float *qlin, *klin, *vlin, *att;
    unsigned *xc, *wqc, *wkc, *wvc, *woc;
    cudaGetSymbolAddress((void**)&qlin, g_qlin);
    cudaGetSymbolAddress((void**)&klin, g_klin);
    cudaGetSymbolAddress((void**)&vlin, g_vlin);
    cudaGetSymbolAddress((void**)&att,  g_att);
    cudaGetSymbolAddress((void**)&xc,   g_xc);
    cudaGetSymbolAddress((void**)&wqc,  g_wqc);
    cudaGetSymbolAddress((void**)&wkc,  g_wkc);
    cudaGetSymbolAddress((void**)&wvc,  g_wvc);
    cudaGetSymbolAddress((void**)&woc,  g_woc);

    const int M = BB*SS;   // 4096

    static bool attr_set = false;
    if (!attr_set) {
        cudaFuncSetAttribute(gemm3, cudaFuncAttributeMaxDynamicSharedMemorySize, GSMEM);
        cudaFuncSetAttribute(attn_mma_kernel, cudaFuncAttributeMaxDynamicSharedMemorySize, ASMEM);
        attr_set = true;
    }

    prep_kernel<<<PREP_BLOCKS, 256>>>(x, Wq, Wk, Wv, Wo);

    gemm3<<<dim3(12, M/TBM), 256, GSMEM>>>(xc,
                                    wqc, qlin, 8, DD,
                                    wkc, klin, 2, HKV*HDIM,
                                    wvc, vlin, 2, HKV*HDIM,
                                    nullptr, DD);

    rope_sp_all<<<(BB*SS*(HH+HKV) + 255)/256, 256>>>(Ws, bs);

    attn_mma_kernel<<<dim3(SS/AQT, HH, BB), 256, ASMEM>>>();

    gemm3<<<dim3(8, M/TBM), 256, GSMEM>>>((const unsigned*)att,
                                    woc, out, 8, DD,
                                    nullptr, nullptr, 0, 0,
                                    nullptr, nullptr, 0, 0,
                                    bo, DD);
}

// round 14
// speedup vs baseline: 1.4784x; 1.2336x over previous
#include <cuda_runtime.h>
#include <cuda_bf16.h>
#include <cuda_fp16.h>
#include <math.h>

#define BB 2
#define SS 2048
#define DD 1024
#define HH 16
#define HKV 4
#define HDIM 64
#define SDIM 16

// ---------------- scratch (device globals; no allocation) ----------------
__device__ float    g_qlin[BB*SS*DD];
__device__ float    g_klin[BB*SS*HKV*HDIM];
__device__ float    g_vlin[BB*SS*HKV*HDIM];
// fp16 (half2-packed) operands
__device__ unsigned g_qh  [BB*HH*SS*HDIM/2];
__device__ unsigned g_qsph[BB*HH*SS*SDIM/2];
__device__ unsigned g_kh  [BB*HKV*SS*HDIM/2];
__device__ unsigned g_ksph[BB*HKV*SS*SDIM/2];
__device__ unsigned g_vh  [BB*HKV*SS*HDIM/2];
__device__ unsigned g_atth[BB*SS*DD/2];
__device__ unsigned g_xh  [BB*SS*DD/2];
__device__ unsigned g_wqh [DD*DD/2];
__device__ unsigned g_wkh [HKV*HDIM*DD/2];
__device__ unsigned g_wvh [HKV*HDIM*DD/2];
__device__ unsigned g_woh [DD*DD/2];
__device__ float    g_cosT[SS*(HDIM/2)];
__device__ float    g_sinT[SS*(HDIM/2)];

// ---------------- common helpers ----------------
__device__ __forceinline__ float ex2f(float x) {
    float r; asm("ex2.approx.f32 %0, %1;" : "=f"(r) : "f"(x)); return r;
}
__device__ __forceinline__ float rcpf(float x) {
    float r; asm("rcp.approx.f32 %0, %1;" : "=f"(r) : "f"(x)); return r;
}
__device__ __forceinline__ float tanhf_a(float x) {
    float r; asm("tanh.approx.f32 %0, %1;" : "=f"(r) : "f"(x)); return r;
}
// pack {lo=a, hi=b} into half2 bits
__device__ __forceinline__ unsigned packh2(float a, float b) {
    unsigned r; asm("cvt.rn.f16x2.f32 %0, %1, %2;" : "=r"(r) : "f"(b), "f"(a)); return r;
}
__device__ __forceinline__ void mma_f16(float& d0, float& d1, float& d2, float& d3,
                                        unsigned a0, unsigned a1, unsigned a2, unsigned a3,
                                        unsigned b0, unsigned b1) {
    asm volatile(
        "mma.sync.aligned.m16n8k16.row.col.f32.f16.f16.f32 "
        "{%0,%1,%2,%3},{%4,%5,%6,%7},{%8,%9},{%0,%1,%2,%3};"
        : "+f"(d0), "+f"(d1), "+f"(d2), "+f"(d3)
        : "r"(a0), "r"(a1), "r"(a2), "r"(a3), "r"(b0), "r"(b1));
}
__device__ __forceinline__ unsigned smem_u32(const void* p) {
    return (unsigned)__cvta_generic_to_shared(p);
}
__device__ __forceinline__ void cp16(unsigned dst, const void* src) {
    asm volatile("cp.async.cg.shared.global [%0], [%1], 16;" :: "r"(dst), "l"(src));
}
__device__ __forceinline__ uint4 ldsm4(unsigned addr) {
    uint4 r;
    asm volatile("ldmatrix.sync.aligned.m8n8.x4.shared.b16 {%0,%1,%2,%3}, [%4];"
                 : "=r"(r.x), "=r"(r.y), "=r"(r.z), "=r"(r.w) : "r"(addr));
    return r;
}
__device__ __forceinline__ uint4 ldsm4t(unsigned addr) {
    uint4 r;
    asm volatile("ldmatrix.sync.aligned.m8n8.x4.trans.shared.b16 {%0,%1,%2,%3}, [%4];"
                 : "=r"(r.x), "=r"(r.y), "=r"(r.z), "=r"(r.w) : "r"(addr));
    return r;
}

// ---------------- fused prologue: rope table + all fp16 conversions ----------------
// Each cvt block packs 2048 floats (256 threads x 8 floats).
// x:2048 | Wq:512 | Wk:128 | Wv:128 | Wo:512 | rope:256  -> 3584 blocks
#define PREP_BLOCKS 3584

__device__ __forceinline__ void cvt_seg_h(const float* __restrict__ in,
                                          unsigned* __restrict__ out, int blk) {
    int i = blk*256 + threadIdx.x;
    float4 f0 = ((const float4*)in)[2*i];
    float4 f1 = ((const float4*)in)[2*i+1];
    uint4 u;
    u.x = packh2(f0.x, f0.y); u.y = packh2(f0.z, f0.w);
    u.z = packh2(f1.x, f1.y); u.w = packh2(f1.z, f1.w);
    ((uint4*)out)[i] = u;
}

__global__ void prep_kernel(const float* __restrict__ x,
                            const float* __restrict__ Wq,
                            const float* __restrict__ Wk,
                            const float* __restrict__ Wv,
                            const float* __restrict__ Wo)
{
    int bx = blockIdx.x;
    if (bx < 2048)      { cvt_seg_h(x,  g_xh,  bx); }
    else if (bx < 2560) { cvt_seg_h(Wq, g_wqh, bx - 2048); }
    else if (bx < 2688) { cvt_seg_h(Wk, g_wkh, bx - 2560); }
    else if (bx < 2816) { cvt_seg_h(Wv, g_wvh, bx - 2688); }
    else if (bx < 3328) { cvt_seg_h(Wo, g_woh, bx - 2816); }
    else {
        int idx = (bx - 3328)*256 + threadIdx.x;   // < 65536
        int s = idx / (HDIM/2), i = idx % (HDIM/2);
        float thf = (float)pow(10000.0, -(double)i / (double)(HDIM/2));
        float ff  = (float)s * thf;
        g_cosT[idx] = (float)cos((double)ff);
        g_sinT[idx] = (float)sin((double)ff);
    }
}

// ================= FP16 m16n8k16 GEMM: C[M,N] = A[M,K] @ W[N,K]^T (+bias) =================
// A/W half2-packed. block 128x128, 8 warps (2m x 4n), BK=32 halves, 3-stage cp.async.
#define TBM 128
#define TBN 128
#define RSTB 80     // smem row stride BYTES (64B data + 16B pad)
#define STG 3
#define GSMEM (STG*(TBM+TBN)*RSTB)

__global__ void __launch_bounds__(256) gemm3h(
    const unsigned* __restrict__ A,
    const unsigned* __restrict__ W0, float* __restrict__ C0, int nx0, int N0,
    const unsigned* __restrict__ W1, float* __restrict__ C1, int nx1, int N1,
    const unsigned* __restrict__ W2, float* __restrict__ C2, int nx2, int N2,
    const float* __restrict__ bias, int K)
{
    extern __shared__ unsigned sh[];
    const int tid = threadIdx.x;
    const int w = tid >> 5, lane = tid & 31;
    const int gid = lane >> 2, t4 = lane & 3;
    const int wm = w & 1, wn = w >> 1;
    const int row0 = blockIdx.y*TBM;
    const int K2 = K >> 1;                       // row stride in unsigned

    const unsigned* Wp; float* Cp; int N, cb;
    int bx = blockIdx.x;
    if (bx < nx0)            { Wp = W0; Cp = C0; N = N0; cb = bx; }
    else if (bx < nx0 + nx1) { Wp = W1; Cp = C1; N = N1; cb = bx - nx0; }
    else                     { Wp = W2; Cp = C2; N = N2; cb = bx - nx0 - nx1; }
    const int col0 = cb*TBN;

    const unsigned* Aptr = A  + (size_t)row0*K2;
    const unsigned* Wptr = Wp + (size_t)col0*K2;

    const unsigned asA = smem_u32(sh);
    const unsigned asB = asA + STG*TBM*RSTB;

    // cp.async: tile = 128 rows x 64B = 512 chunks of 16B; 2 per thread per operand
    const int cr = tid >> 1, cc16 = tid & 1;     // row, 16B-pair selector base
    // each thread does chunks (cr, cc16*2) and (cr, cc16*2+1)

    // ldsm byte offsets within a stage
    const int kRow = ((lane >> 4) << 3) | (lane & 7);
    const int kCol = ((lane >> 3) & 1) << 3;     // halves
    int aoffB[4], boffB[2];
    #pragma unroll
    for (int mt = 0; mt < 4; mt++)
        aoffB[mt] = (wm*64 + mt*16 + (lane & 15))*RSTB + ((lane >> 4) << 4);
    #pragma unroll
    for (int np = 0; np < 2; np++)
        boffB[np] = (wn*32 + np*16 + kRow)*RSTB + kCol*2;

    #pragma unroll
    for (int s = 0; s < STG-1; s++) {
        int kh2 = s*16;                          // stage k-offset in unsigned
        #pragma unroll
        for (int c = 0; c < 2; c++) {
            int c16 = cc16*2 + c;
            cp16(asA + s*(TBM*RSTB) + cr*RSTB + c16*16, Aptr + (size_t)cr*K2 + kh2 + c16*4);
            cp16(asB + s*(TBN*RSTB) + cr*RSTB + c16*16, Wptr + (size_t)cr*K2 + kh2 + c16*4);
        }
        asm volatile("cp.async.commit_group;");
    }

    float acc[4][4][4];
    #pragma unroll
    for (int mt = 0; mt < 4; mt++)
        #pragma unroll
        for (int nt = 0; nt < 4; nt++)
            #pragma unroll
            for (int j = 0; j < 4; j++) acc[mt][nt][j] = 0.f;

    const int T = K / 32;                        // stages of 32 halves
    int st = 0, si = STG - 1;
    for (int t = 0; t < T; t++) {
        asm volatile("cp.async.wait_group 1;" ::: "memory");
        __syncthreads();

        if (t + STG - 1 < T) {
            int kh2 = (t + STG - 1)*16;
            #pragma unroll
            for (int c = 0; c < 2; c++) {
                int c16 = cc16*2 + c;
                cp16(asA + si*(TBM*RSTB) + cr*RSTB + c16*16, Aptr + (size_t)cr*K2 + kh2 + c16*4);
                cp16(asB + si*(TBN*RSTB) + cr*RSTB + c16*16, Wptr + (size_t)cr*K2 + kh2 + c16*4);
            }
        }
        asm volatile("cp.async.commit_group;");

        const unsigned aStg = asA + st*(TBM*RSTB);
        const unsigned bStg = asB + st*(TBN*RSTB);
        #pragma unroll
        for (int k16 = 0; k16 < 2; k16++) {
            const int kb = k16*32;               // bytes
            uint4 av[4], bv[2];
            #pragma unroll
            for (int mt = 0; mt < 4; mt++) av[mt] = ldsm4(aStg + aoffB[mt] + kb);
            #pragma unroll
            for (int np = 0; np < 2; np++) bv[np] = ldsm4(bStg + boffB[np] + kb);
            #pragma unroll
            for (int np = 0; np < 2; np++) {
                #pragma unroll
                for (int mt = 0; mt < 4; mt++) {
                    mma_f16(acc[mt][2*np  ][0], acc[mt][2*np  ][1], acc[mt][2*np  ][2], acc[mt][2*np  ][3],
                            av[mt].x, av[mt].y, av[mt].z, av[mt].w, bv[np].x, bv[np].y);
                    mma_f16(acc[mt][2*np+1][0], acc[mt][2*np+1][1], acc[mt][2*np+1][2], acc[mt][2*np+1][3],
                            av[mt].x, av[mt].y, av[mt].z, av[mt].w, bv[np].z, bv[np].w);
                }
            }
        }
        st = (st + 1 == STG) ? 0 : st + 1;
        si = (si + 1 == STG) ? 0 : si + 1;
    }

    #pragma unroll
    for (int mt = 0; mt < 4; mt++) {
        int r = row0 + wm*64 + mt*16 + gid;
        #pragma unroll
        for (int nt = 0; nt < 4; nt++) {
            int c = col0 + wn*32 + nt*8 + 2*t4;
            float bv0 = bias ? bias[c]   : 0.f;
            float bv1 = bias ? bias[c+1] : 0.f;
            *(float2*)&Cp[(size_t)r*N + c]     = make_float2(acc[mt][nt][0]+bv0, acc[mt][nt][1]+bv1);
            *(float2*)&Cp[(size_t)(r+8)*N + c] = make_float2(acc[mt][nt][2]+bv0, acc[mt][nt][3]+bv1);
        }
    }
}

// ---------------- fused RoPE + sparsity projection -> fp16 outputs ----------------
__global__ void rope_sp_all(const float* __restrict__ Ws,
                            const float* __restrict__ bs)
{
    __shared__ float WsS[SDIM*HDIM];
    __shared__ float bsS[SDIM];
    for (int i = threadIdx.x; i < SDIM*HDIM; i += blockDim.x) WsS[i] = Ws[i];
    if (threadIdx.x < SDIM) bsS[threadIdx.x] = bs[threadIdx.x];
    __syncthreads();

    const int NQ = BB*SS*HH;
    int gidx = blockIdx.x*blockDim.x + threadIdx.x;

    const float* lin; unsigned *obuf, *spbuf;
    bool doV = false;
    int b, s, h, NH;
    if (gidx < NQ) {
        NH = HH;
        h = gidx % NH; s = (gidx / NH) % SS; b = gidx / (NH*SS);
        lin = g_qlin; obuf = g_qh; spbuf = g_qsph;
    } else {
        int idx = gidx - NQ;
        if (idx >= BB*SS*HKV) return;
        NH = HKV;
        s = idx % SS; h = (idx / SS) % HKV; b = idx / (SS*HKV);
        lin = g_klin; obuf = g_kh; spbuf = g_ksph;
        doV = true;
    }

    const float4* src = (const float4*)(lin + ((size_t)(b*SS + s)*NH + h)*HDIM);
    float v[HDIM];
    #pragma unroll
    for (int t = 0; t < HDIM/4; t++) ((float4*)v)[t] = src[t];

    #pragma unroll
    for (int i = 0; i < HDIM/2; i++) {
        float c  = g_cosT[s*(HDIM/2)+i];
        float sn = g_sinT[s*(HDIM/2)+i];
        float a  = v[i], bpart = v[i+HDIM/2];
        v[i]        = a*c - bpart*sn;
        v[i+HDIM/2] = bpart*c + a*sn;
    }

    unsigned hh[HDIM/2];
    #pragma unroll
    for (int d = 0; d < HDIM/2; d++) hh[d] = packh2(v[2*d], v[2*d+1]);
    unsigned* dst = obuf + (((size_t)b*NH + h)*SS + s)*(HDIM/2);
    #pragma unroll
    for (int t = 0; t < HDIM/8; t++) ((uint4*)dst)[t] = ((uint4*)hh)[t];

    float sp[SDIM];
    #pragma unroll
    for (int j = 0; j < SDIM; j++) {
        float acc = bsS[j];
        #pragma unroll
        for (int d = 0; d < HDIM; d++) acc += WsS[j*HDIM + d] * v[d];
        sp[j] = acc;
    }
    unsigned* spd = spbuf + (((size_t)b*NH + h)*SS + s)*(SDIM/2);
    #pragma unroll
    for (int j = 0; j < SDIM/2; j++) spd[j] = packh2(sp[2*j], sp[2*j+1]);

    if (doV) {
        const float* vsrc = g_vlin + ((size_t)(b*SS + s)*NH + h)*HDIM;
        unsigned vv[HDIM/2];
        #pragma unroll
        for (int d = 0; d < HDIM/2; d++) vv[d] = packh2(vsrc[2*d], vsrc[2*d+1]);
        unsigned* vdst = g_vh + (((size_t)b*HKV + h)*SS + s)*(HDIM/2);
        #pragma unroll
        for (int t = 0; t < HDIM/8; t++) ((uint4*)vdst)[t] = ((uint4*)vv)[t];
    }
}

// ================= FP16 m16n8k16 attention =================
#define AQT 128
#define AKT 64
#define KSTRB 144
#define SSTRB 48
#define KBUFB (AKT*KSTRB)
#define VBUFB (AKT*KSTRB)
#define SBUFB (AKT*SSTRB)
#define ABUFB (KBUFB+VBUFB+SBUFB)
#define ASMEM (2*ABUFB)

#define C_QK 0.1803368801f    // 0.125 * log2(e)

__global__ void __launch_bounds__(256, 2) attn_mma_kernel()
{
    extern __shared__ unsigned ash[];

    const int b = blockIdx.z, h = blockIdx.y;
    const int hkv = h >> 2;
    const int q0 = (gridDim.x - 1 - blockIdx.x) * AQT;
    const int tid = threadIdx.x;
    const int w = tid >> 5, lane = tid & 31;
    const int gid = lane >> 2, t4 = lane & 3;

    const int q0w = q0 + w*16;
    const int qr0 = q0w + gid;
    const int qr1 = qr0 + 8;

    const unsigned* qh2  = g_qh  + ((size_t)b*HH  + h  )*SS*(HDIM/2);
    const unsigned* qsph = g_qsph+ ((size_t)b*HH  + h  )*SS*(SDIM/2);
    const unsigned* kh2  = g_kh  + ((size_t)b*HKV + hkv)*SS*(HDIM/2);
    const unsigned* ksph = g_ksph+ ((size_t)b*HKV + hkv)*SS*(SDIM/2);
    const unsigned* vh2  = g_vh  + ((size_t)b*HKV + hkv)*SS*(HDIM/2);

    const unsigned shbase = smem_u32(ash);

    const int kRow = ((lane >> 4) << 3) | (lane & 7);
    const int kCol = ((lane >> 3) & 1) << 3;
    const int vRow = (((lane >> 3) & 1) << 3) | (lane & 7);
    const int vCol = (lane >> 4) << 3;

    unsigned qa[4][4], qsa[4];
    #pragma unroll
    for (int kt = 0; kt < 4; kt++) {
        qa[kt][0] = qh2[(size_t)qr0*(HDIM/2) + kt*8 + t4];
        qa[kt][1] = qh2[(size_t)qr1*(HDIM/2) + kt*8 + t4];
        qa[kt][2] = qh2[(size_t)qr0*(HDIM/2) + kt*8 + t4 + 4];
        qa[kt][3] = qh2[(size_t)qr1*(HDIM/2) + kt*8 + t4 + 4];
    }
    qsa[0] = qsph[(size_t)qr0*(SDIM/2) + t4];
    qsa[1] = qsph[(size_t)qr1*(SDIM/2) + t4];
    qsa[2] = qsph[(size_t)qr0*(SDIM/2) + t4 + 4];
    qsa[3] = qsph[(size_t)qr1*(SDIM/2) + t4 + 4];

    float l0 = 0.f, l1 = 0.f;
    float O[8][4];
    #pragma unroll
    for (int dn = 0; dn < 8; dn++)
        #pragma unroll
        for (int j = 0; j < 4; j++) O[dn][j] = 0.f;

    auto issue_tile = [&](int kb, int buf) {
        unsigned base = shbase + buf*ABUFB;
        #pragma unroll
        for (int c = 0; c < 2; c++) {
            int i = tid + c*256;
            int key = i >> 3, c8 = i & 7;
            cp16(base + key*KSTRB + c8*16,          kh2 + (size_t)(kb+key)*(HDIM/2) + c8*4);
            cp16(base + KBUFB + key*KSTRB + c8*16,  vh2 + (size_t)(kb+key)*(HDIM/2) + c8*4);
        }
        if (tid < 128) {
            int key = tid >> 1, c2 = tid & 1;
            cp16(base + KBUFB + VBUFB + key*SSTRB + c2*16,
                 ksph + (size_t)(kb+key)*(SDIM/2) + c2*4);
        }
    };

    const int nTiles = (q0 + AQT) / AKT;
    issue_tile(0, 0);
    asm volatile("cp.async.commit_group;");

    for (int t = 0; t < nTiles; t++) {
        const int kb = t*AKT;
        const int buf = t & 1;
        __syncthreads();
        if (t + 1 < nTiles) issue_tile(kb + AKT, buf ^ 1);
        asm volatile("cp.async.commit_group;");
        asm volatile("cp.async.wait_group 1;" ::: "memory");
        __syncthreads();

        if (kb > q0w + 15) continue;

        const unsigned kBase  = shbase + buf*ABUFB;
        const unsigned vBase  = kBase + KBUFB;
        const unsigned spBase = kBase + KBUFB + VBUFB;

        float S[8][4];
        #pragma unroll
        for (int nt = 0; nt < 8; nt++)
            #pragma unroll
            for (int j = 0; j < 4; j++) S[nt][j] = 0.f;

        #pragma unroll
        for (int kt = 0; kt < 4; kt++) {
            #pragma unroll
            for (int g2 = 0; g2 < 4; g2++) {
                uint4 bb = ldsm4(kBase + (g2*16 + kRow)*KSTRB + (kt*16 + kCol)*2);
                mma_f16(S[2*g2  ][0], S[2*g2  ][1], S[2*g2  ][2], S[2*g2  ][3],
                        qa[kt][0], qa[kt][1], qa[kt][2], qa[kt][3], bb.x, bb.y);
                mma_f16(S[2*g2+1][0], S[2*g2+1][1], S[2*g2+1][2], S[2*g2+1][3],
                        qa[kt][0], qa[kt][1], qa[kt][2], qa[kt][3], bb.z, bb.w);
            }
        }

        #pragma unroll
        for (int g2 = 0; g2 < 4; g2++) {
            float sp0[4] = {0.f,0.f,0.f,0.f}, sp1[4] = {0.f,0.f,0.f,0.f};
            uint4 bb = ldsm4(spBase + (g2*16 + kRow)*SSTRB + kCol*2);
            mma_f16(sp0[0], sp0[1], sp0[2], sp0[3],
                    qsa[0], qsa[1], qsa[2], qsa[3], bb.x, bb.y);
            mma_f16(sp1[0], sp1[1], sp1[2], sp1[3],
                    qsa[0], qsa[1], qsa[2], qsa[3], bb.z, bb.w);

            #pragma unroll
            for (int j = 0; j < 4; j++) {
                {
                    int key = kb + (2*g2)*8 + 2*t4 + (j & 1);
                    int row = (j >= 2) ? qr1 : qr0;
                    float gf = fmaf(0.5f, tanhf_a(sp0[j] * 0.125f), 0.5f);
                    float p  = (key > row) ? 0.f : ex2f(S[2*g2][j] * C_QK * gf);
                    S[2*g2][j] = p;
                    if (j >= 2) l1 += p; else l0 += p;
                }
                {
                    int key = kb + (2*g2+1)*8 + 2*t4 + (j & 1);
                    int row = (j >= 2) ? qr1 : qr0;
                    float gf = fmaf(0.5f, tanhf_a(sp1[j] * 0.125f), 0.5f);
                    float p  = (key > row) ? 0.f : ex2f(S[2*g2+1][j] * C_QK * gf);
                    S[2*g2+1][j] = p;
                    if (j >= 2) l1 += p; else l0 += p;
                }
            }
        }

        #pragma unroll
        for (int kt = 0; kt < 4; kt++) {
            unsigned a0 = packh2(S[2*kt  ][0], S[2*kt  ][1]);
            unsigned a1 = packh2(S[2*kt  ][2], S[2*kt  ][3]);
            unsigned a2 = packh2(S[2*kt+1][0], S[2*kt+1][1]);
            unsigned a3 = packh2(S[2*kt+1][2], S[2*kt+1][3]);

            #pragma unroll
            for (int dnp = 0; dnp < 4; dnp++) {
                uint4 bb = ldsm4t(vBase + (kt*16 + vRow)*KSTRB + (dnp*16 + vCol)*2);
                mma_f16(O[2*dnp  ][0], O[2*dnp  ][1], O[2*dnp  ][2], O[2*dnp  ][3],
                        a0, a1, a2, a3, bb.x, bb.y);
                mma_f16(O[2*dnp+1][0], O[2*dnp+1][1], O[2*dnp+1][2], O[2*dnp+1][3],
                        a0, a1, a2, a3, bb.z, bb.w);
            }
        }
    }

    // epilogue: reduce l across quad, normalize, pack half2 for O GEMM
    #pragma unroll
    for (int off = 1; off < 4; off <<= 1) {
        l0 += __shfl_xor_sync(0xffffffffu, l0, off);
        l1 += __shfl_xor_sync(0xffffffffu, l1, off);
    }
    float inv0 = rcpf(l0), inv1 = rcpf(l1);
    #pragma unroll
    for (int dn = 0; dn < 8; dn++) {
        int col2 = (h*HDIM + dn*8 + 2*t4) >> 1;   // half2 index
        g_atth[((size_t)b*SS + qr0)*(DD/2) + col2] = packh2(O[dn][0]*inv0, O[dn][1]*inv0);
        g_atth[((size_t)b*SS + qr1)*(DD/2) + col2] = packh2(O[dn][2]*inv1, O[dn][3]*inv1);
    }
}

// ---------------- launch ----------------
extern "C" void kernel_launch(void* const* d_in, const int* in_sizes, int n_in,
                              void* d_out, int out_size)
{
    (void)in_sizes; (void)n_in; (void)out_size;
    const float* x  = (const float*)d_in[0];
    const float* Wq = (const float*)d_in[1];
    const float* Wk = (const float*)d_in[2];
    const float* Wv = (const float*)d_in[3];
    const float* Wo = (const float*)d_in[4];
    const float* bo = (const float*)d_in[5];
    const float* Ws = (const float*)d_in[6];
    const float* bs = (const float*)d_in[7];
    float* out = (float*)d_out;

    float *qlin, *klin, *vlin;
    unsigned *xh, *wqh, *wkh, *wvh, *woh, *atth;
    cudaGetSymbolAddress((void**)&qlin, g_qlin);
    cudaGetSymbolAddress((void**)&klin, g_klin);
    cudaGetSymbolAddress((void**)&vlin, g_vlin);
    cudaGetSymbolAddress((void**)&xh,   g_xh);
    cudaGetSymbolAddress((void**)&wqh,  g_wqh);
    cudaGetSymbolAddress((void**)&wkh,  g_wkh);
    cudaGetSymbolAddress((void**)&wvh,  g_wvh);
    cudaGetSymbolAddress((void**)&woh,  g_woh);
    cudaGetSymbolAddress((void**)&atth, g_atth);

    const int M = BB*SS;   // 4096

    static bool attr_set = false;
    if (!attr_set) {
        cudaFuncSetAttribute(gemm3h, cudaFuncAttributeMaxDynamicSharedMemorySize, GSMEM);
        cudaFuncSetAttribute(attn_mma_kernel, cudaFuncAttributeMaxDynamicSharedMemorySize, ASMEM);
        attr_set = true;
    }

    prep_kernel<<<PREP_BLOCKS, 256>>>(x, Wq, Wk, Wv, Wo);

    gemm3h<<<dim3(12, M/TBM), 256, GSMEM>>>(xh,
                                    wqh, qlin, 8, DD,
                                    wkh, klin, 2, HKV*HDIM,
                                    wvh, vlin, 2, HKV*HDIM,
                                    nullptr, DD);

    rope_sp_all<<<(BB*SS*(HH+HKV) + 255)/256, 256>>>(Ws, bs);

    attn_mma_kernel<<<dim3(SS/AQT, HH, BB), 256, ASMEM>>>();

    gemm3h<<<dim3(8, M/TBM), 256, GSMEM>>>(atth,
                                    woh, out, 8, DD,
                                    nullptr, nullptr, 0, 0,
                                    nullptr, nullptr, 0, 0,
                                    bo, DD);
}

// round 15
// speedup vs baseline: 1.5329x; 1.0369x over previous
#include <cuda_runtime.h>
#include <cuda_bf16.h>
#include <cuda_fp16.h>
#include <math.h>

#define BB 2
#define SS 2048
#define DD 1024
#define HH 16
#define HKV 4
#define HDIM 64
#define SDIM 16

// ---------------- scratch (device globals; no allocation) ----------------
__device__ float    g_qlin[BB*SS*DD];
__device__ float    g_klin[BB*SS*HKV*HDIM];
__device__ float    g_vlin[BB*SS*HKV*HDIM];
__device__ unsigned g_qh  [BB*HH*SS*HDIM/2];
__device__ unsigned g_qsph[BB*HH*SS*SDIM/2];
__device__ unsigned g_kh  [BB*HKV*SS*HDIM/2];
__device__ unsigned g_ksph[BB*HKV*SS*SDIM/2];
__device__ unsigned g_vh  [BB*HKV*SS*HDIM/2];
__device__ unsigned g_atth[BB*SS*DD/2];
__device__ unsigned g_xh  [BB*SS*DD/2];
__device__ unsigned g_wqh [DD*DD/2];
__device__ unsigned g_wkh [HKV*HDIM*DD/2];
__device__ unsigned g_wvh [HKV*HDIM*DD/2];
__device__ unsigned g_woh [DD*DD/2];
__device__ float    g_cosT[SS*(HDIM/2)];
__device__ float    g_sinT[SS*(HDIM/2)];

// ---------------- common helpers ----------------
__device__ __forceinline__ float ex2f(float x) {
    float r; asm("ex2.approx.f32 %0, %1;" : "=f"(r) : "f"(x)); return r;
}
__device__ __forceinline__ float rcpf(float x) {
    float r; asm("rcp.approx.f32 %0, %1;" : "=f"(r) : "f"(x)); return r;
}
__device__ __forceinline__ float tanhf_a(float x) {
    float r; asm("tanh.approx.f32 %0, %1;" : "=f"(r) : "f"(x)); return r;
}
__device__ __forceinline__ unsigned packh2(float a, float b) {
    unsigned r; asm("cvt.rn.f16x2.f32 %0, %1, %2;" : "=r"(r) : "f"(b), "f"(a)); return r;
}
__device__ __forceinline__ void mma_f16(float& d0, float& d1, float& d2, float& d3,
                                        unsigned a0, unsigned a1, unsigned a2, unsigned a3,
                                        unsigned b0, unsigned b1) {
    asm volatile(
        "mma.sync.aligned.m16n8k16.row.col.f32.f16.f16.f32 "
        "{%0,%1,%2,%3},{%4,%5,%6,%7},{%8,%9},{%0,%1,%2,%3};"
        : "+f"(d0), "+f"(d1), "+f"(d2), "+f"(d3)
        : "r"(a0), "r"(a1), "r"(a2), "r"(a3), "r"(b0), "r"(b1));
}
__device__ __forceinline__ unsigned smem_u32(const void* p) {
    return (unsigned)__cvta_generic_to_shared(p);
}
__device__ __forceinline__ void cp16(unsigned dst, const void* src) {
    asm volatile("cp.async.cg.shared.global [%0], [%1], 16;" :: "r"(dst), "l"(src));
}
__device__ __forceinline__ uint4 ldsm4(unsigned addr) {
    uint4 r;
    asm volatile("ldmatrix.sync.aligned.m8n8.x4.shared.b16 {%0,%1,%2,%3}, [%4];"
                 : "=r"(r.x), "=r"(r.y), "=r"(r.z), "=r"(r.w) : "r"(addr));
    return r;
}
__device__ __forceinline__ uint4 ldsm4t(unsigned addr) {
    uint4 r;
    asm volatile("ldmatrix.sync.aligned.m8n8.x4.trans.shared.b16 {%0,%1,%2,%3}, [%4];"
                 : "=r"(r.x), "=r"(r.y), "=r"(r.z), "=r"(r.w) : "r"(addr));
    return r;
}

// ---------------- fused prologue: rope table + all fp16 conversions ----------------
#define PREP_BLOCKS 3584

__device__ __forceinline__ void cvt_seg_h(const float* __restrict__ in,
                                          unsigned* __restrict__ out, int blk) {
    int i = blk*256 + threadIdx.x;
    float4 f0 = ((const float4*)in)[2*i];
    float4 f1 = ((const float4*)in)[2*i+1];
    uint4 u;
    u.x = packh2(f0.x, f0.y); u.y = packh2(f0.z, f0.w);
    u.z = packh2(f1.x, f1.y); u.w = packh2(f1.z, f1.w);
    ((uint4*)out)[i] = u;
}

__global__ void prep_kernel(const float* __restrict__ x,
                            const float* __restrict__ Wq,
                            const float* __restrict__ Wk,
                            const float* __restrict__ Wv,
                            const float* __restrict__ Wo)
{
    int bx = blockIdx.x;
    if (bx < 2048)      { cvt_seg_h(x,  g_xh,  bx); }
    else if (bx < 2560) { cvt_seg_h(Wq, g_wqh, bx - 2048); }
    else if (bx < 2688) { cvt_seg_h(Wk, g_wkh, bx - 2560); }
    else if (bx < 2816) { cvt_seg_h(Wv, g_wvh, bx - 2688); }
    else if (bx < 3328) { cvt_seg_h(Wo, g_woh, bx - 2816); }
    else {
        int idx = (bx - 3328)*256 + threadIdx.x;
        int s = idx / (HDIM/2), i = idx % (HDIM/2);
        float thf = (float)pow(10000.0, -(double)i / (double)(HDIM/2));
        float ff  = (float)s * thf;
        g_cosT[idx] = (float)cos((double)ff);
        g_sinT[idx] = (float)sin((double)ff);
    }
}

// ================= FP16 m16n8k16 GEMM (unchanged from R13) =================
#define TBM 128
#define TBN 128
#define RSTB 80
#define STG 3
#define GSMEM (STG*(TBM+TBN)*RSTB)

__global__ void __launch_bounds__(256) gemm3h(
    const unsigned* __restrict__ A,
    const unsigned* __restrict__ W0, float* __restrict__ C0, int nx0, int N0,
    const unsigned* __restrict__ W1, float* __restrict__ C1, int nx1, int N1,
    const unsigned* __restrict__ W2, float* __restrict__ C2, int nx2, int N2,
    const float* __restrict__ bias, int K)
{
    extern __shared__ unsigned sh[];
    const int tid = threadIdx.x;
    const int w = tid >> 5, lane = tid & 31;
    const int gid = lane >> 2, t4 = lane & 3;
    const int wm = w & 1, wn = w >> 1;
    const int row0 = blockIdx.y*TBM;
    const int K2 = K >> 1;

    const unsigned* Wp; float* Cp; int N, cb;
    int bx = blockIdx.x;
    if (bx < nx0)            { Wp = W0; Cp = C0; N = N0; cb = bx; }
    else if (bx < nx0 + nx1) { Wp = W1; Cp = C1; N = N1; cb = bx - nx0; }
    else                     { Wp = W2; Cp = C2; N = N2; cb = bx - nx0 - nx1; }
    const int col0 = cb*TBN;

    const unsigned* Aptr = A  + (size_t)row0*K2;
    const unsigned* Wptr = Wp + (size_t)col0*K2;

    const unsigned asA = smem_u32(sh);
    const unsigned asB = asA + STG*TBM*RSTB;

    const int cr = tid >> 1, cc16 = tid & 1;

    const int kRow = ((lane >> 4) << 3) | (lane & 7);
    const int kCol = ((lane >> 3) & 1) << 3;
    int aoffB[4], boffB[2];
    #pragma unroll
    for (int mt = 0; mt < 4; mt++)
        aoffB[mt] = (wm*64 + mt*16 + (lane & 15))*RSTB + ((lane >> 4) << 4);
    #pragma unroll
    for (int np = 0; np < 2; np++)
        boffB[np] = (wn*32 + np*16 + kRow)*RSTB + kCol*2;

    #pragma unroll
    for (int s = 0; s < STG-1; s++) {
        int kh2 = s*16;
        #pragma unroll
        for (int c = 0; c < 2; c++) {
            int c16 = cc16*2 + c;
            cp16(asA + s*(TBM*RSTB) + cr*RSTB + c16*16, Aptr + (size_t)cr*K2 + kh2 + c16*4);
            cp16(asB + s*(TBN*RSTB) + cr*RSTB + c16*16, Wptr + (size_t)cr*K2 + kh2 + c16*4);
        }
        asm volatile("cp.async.commit_group;");
    }

    float acc[4][4][4];
    #pragma unroll
    for (int mt = 0; mt < 4; mt++)
        #pragma unroll
        for (int nt = 0; nt < 4; nt++)
            #pragma unroll
            for (int j = 0; j < 4; j++) acc[mt][nt][j] = 0.f;

    const int T = K / 32;
    int st = 0, si = STG - 1;
    for (int t = 0; t < T; t++) {
        asm volatile("cp.async.wait_group 1;" ::: "memory");
        __syncthreads();

        if (t + STG - 1 < T) {
            int kh2 = (t + STG - 1)*16;
            #pragma unroll
            for (int c = 0; c < 2; c++) {
                int c16 = cc16*2 + c;
                cp16(asA + si*(TBM*RSTB) + cr*RSTB + c16*16, Aptr + (size_t)cr*K2 + kh2 + c16*4);
                cp16(asB + si*(TBN*RSTB) + cr*RSTB + c16*16, Wptr + (size_t)cr*K2 + kh2 + c16*4);
            }
        }
        asm volatile("cp.async.commit_group;");

        const unsigned aStg = asA + st*(TBM*RSTB);
        const unsigned bStg = asB + st*(TBN*RSTB);
        #pragma unroll
        for (int k16 = 0; k16 < 2; k16++) {
            const int kb = k16*32;
            uint4 av[4], bv[2];
            #pragma unroll
            for (int mt = 0; mt < 4; mt++) av[mt] = ldsm4(aStg + aoffB[mt] + kb);
            #pragma unroll
            for (int np = 0; np < 2; np++) bv[np] = ldsm4(bStg + boffB[np] + kb);
            #pragma unroll
            for (int np = 0; np < 2; np++) {
                #pragma unroll
                for (int mt = 0; mt < 4; mt++) {
                    mma_f16(acc[mt][2*np  ][0], acc[mt][2*np  ][1], acc[mt][2*np  ][2], acc[mt][2*np  ][3],
                            av[mt].x, av[mt].y, av[mt].z, av[mt].w, bv[np].x, bv[np].y);
                    mma_f16(acc[mt][2*np+1][0], acc[mt][2*np+1][1], acc[mt][2*np+1][2], acc[mt][2*np+1][3],
                            av[mt].x, av[mt].y, av[mt].z, av[mt].w, bv[np].z, bv[np].w);
                }
            }
        }
        st = (st + 1 == STG) ? 0 : st + 1;
        si = (si + 1 == STG) ? 0 : si + 1;
    }

    #pragma unroll
    for (int mt = 0; mt < 4; mt++) {
        int r = row0 + wm*64 + mt*16 + gid;
        #pragma unroll
        for (int nt = 0; nt < 4; nt++) {
            int c = col0 + wn*32 + nt*8 + 2*t4;
            float bv0 = bias ? bias[c]   : 0.f;
            float bv1 = bias ? bias[c+1] : 0.f;
            *(float2*)&Cp[(size_t)r*N + c]     = make_float2(acc[mt][nt][0]+bv0, acc[mt][nt][1]+bv1);
            *(float2*)&Cp[(size_t)(r+8)*N + c] = make_float2(acc[mt][nt][2]+bv0, acc[mt][nt][3]+bv1);
        }
    }
}

// ---------------- fused RoPE + sparsity projection -> fp16 outputs ----------------
__global__ void rope_sp_all(const float* __restrict__ Ws,
                            const float* __restrict__ bs)
{
    __shared__ float WsS[SDIM*HDIM];
    __shared__ float bsS[SDIM];
    for (int i = threadIdx.x; i < SDIM*HDIM; i += blockDim.x) WsS[i] = Ws[i];
    if (threadIdx.x < SDIM) bsS[threadIdx.x] = bs[threadIdx.x];
    __syncthreads();

    const int NQ = BB*SS*HH;
    int gidx = blockIdx.x*blockDim.x + threadIdx.x;

    const float* lin; unsigned *obuf, *spbuf;
    bool doV = false;
    int b, s, h, NH;
    if (gidx < NQ) {
        NH = HH;
        h = gidx % NH; s = (gidx / NH) % SS; b = gidx / (NH*SS);
        lin = g_qlin; obuf = g_qh; spbuf = g_qsph;
    } else {
        int idx = gidx - NQ;
        if (idx >= BB*SS*HKV) return;
        NH = HKV;
        s = idx % SS; h = (idx / SS) % HKV; b = idx / (SS*HKV);
        lin = g_klin; obuf = g_kh; spbuf = g_ksph;
        doV = true;
    }

    const float4* src = (const float4*)(lin + ((size_t)(b*SS + s)*NH + h)*HDIM);
    float v[HDIM];
    #pragma unroll
    for (int t = 0; t < HDIM/4; t++) ((float4*)v)[t] = src[t];

    #pragma unroll
    for (int i = 0; i < HDIM/2; i++) {
        float c  = g_cosT[s*(HDIM/2)+i];
        float sn = g_sinT[s*(HDIM/2)+i];
        float a  = v[i], bpart = v[i+HDIM/2];
        v[i]        = a*c - bpart*sn;
        v[i+HDIM/2] = bpart*c + a*sn;
    }

    unsigned hh[HDIM/2];
    #pragma unroll
    for (int d = 0; d < HDIM/2; d++) hh[d] = packh2(v[2*d], v[2*d+1]);
    unsigned* dst = obuf + (((size_t)b*NH + h)*SS + s)*(HDIM/2);
    #pragma unroll
    for (int t = 0; t < HDIM/8; t++) ((uint4*)dst)[t] = ((uint4*)hh)[t];

    float sp[SDIM];
    #pragma unroll
    for (int j = 0; j < SDIM; j++) {
        float acc = bsS[j];
        #pragma unroll
        for (int d = 0; d < HDIM; d++) acc += WsS[j*HDIM + d] * v[d];
        sp[j] = acc;
    }
    unsigned* spd = spbuf + (((size_t)b*NH + h)*SS + s)*(SDIM/2);
    #pragma unroll
    for (int j = 0; j < SDIM/2; j++) spd[j] = packh2(sp[2*j], sp[2*j+1]);

    if (doV) {
        const float* vsrc = g_vlin + ((size_t)(b*SS + s)*NH + h)*HDIM;
        unsigned vv[HDIM/2];
        #pragma unroll
        for (int d = 0; d < HDIM/2; d++) vv[d] = packh2(vsrc[2*d], vsrc[2*d+1]);
        unsigned* vdst = g_vh + (((size_t)b*HKV + h)*SS + s)*(HDIM/2);
        #pragma unroll
        for (int t = 0; t < HDIM/8; t++) ((uint4*)vdst)[t] = ((uint4*)vv)[t];
    }
}

// ================= FP16 attention: 16-key slices, short S lifetimes =================
#define AQT 128
#define AKT 64
#define KSTRB 144
#define SSTRB 48
#define KBUFB (AKT*KSTRB)
#define VBUFB (AKT*KSTRB)
#define SBUFB (AKT*SSTRB)
#define ABUFB (KBUFB+VBUFB+SBUFB)
#define ASMEM (2*ABUFB)

#define C_QK 0.1803368801f    // 0.125 * log2(e)

__global__ void __launch_bounds__(256, 2) attn_mma_kernel()
{
    extern __shared__ unsigned ash[];

    const int b = blockIdx.z, h = blockIdx.y;
    const int hkv = h >> 2;
    const int q0 = (gridDim.x - 1 - blockIdx.x) * AQT;
    const int tid = threadIdx.x;
    const int w = tid >> 5, lane = tid & 31;
    const int gid = lane >> 2, t4 = lane & 3;

    const int q0w = q0 + w*16;
    const int qr0 = q0w + gid;
    const int qr1 = qr0 + 8;

    const unsigned* qh2  = g_qh  + ((size_t)b*HH  + h  )*SS*(HDIM/2);
    const unsigned* qsph = g_qsph+ ((size_t)b*HH  + h  )*SS*(SDIM/2);
    const unsigned* kh2  = g_kh  + ((size_t)b*HKV + hkv)*SS*(HDIM/2);
    const unsigned* ksph = g_ksph+ ((size_t)b*HKV + hkv)*SS*(SDIM/2);
    const unsigned* vh2  = g_vh  + ((size_t)b*HKV + hkv)*SS*(HDIM/2);

    const unsigned shbase = smem_u32(ash);

    const int kRow = ((lane >> 4) << 3) | (lane & 7);
    const int kCol = ((lane >> 3) & 1) << 3;
    const int vRow = (((lane >> 3) & 1) << 3) | (lane & 7);
    const int vCol = (lane >> 4) << 3;

    unsigned qa[4][4], qsa[4];
    #pragma unroll
    for (int kt = 0; kt < 4; kt++) {
        qa[kt][0] = qh2[(size_t)qr0*(HDIM/2) + kt*8 + t4];
        qa[kt][1] = qh2[(size_t)qr1*(HDIM/2) + kt*8 + t4];
        qa[kt][2] = qh2[(size_t)qr0*(HDIM/2) + kt*8 + t4 + 4];
        qa[kt][3] = qh2[(size_t)qr1*(HDIM/2) + kt*8 + t4 + 4];
    }
    qsa[0] = qsph[(size_t)qr0*(SDIM/2) + t4];
    qsa[1] = qsph[(size_t)qr1*(SDIM/2) + t4];
    qsa[2] = qsph[(size_t)qr0*(SDIM/2) + t4 + 4];
    qsa[3] = qsph[(size_t)qr1*(SDIM/2) + t4 + 4];

    float l0 = 0.f, l1 = 0.f;
    float O[8][4];
    #pragma unroll
    for (int dn = 0; dn < 8; dn++)
        #pragma unroll
        for (int j = 0; j < 4; j++) O[dn][j] = 0.f;

    auto issue_tile = [&](int kb, int buf) {
        unsigned base = shbase + buf*ABUFB;
        #pragma unroll
        for (int c = 0; c < 2; c++) {
            int i = tid + c*256;
            int key = i >> 3, c8 = i & 7;
            cp16(base + key*KSTRB + c8*16,          kh2 + (size_t)(kb+key)*(HDIM/2) + c8*4);
            cp16(base + KBUFB + key*KSTRB + c8*16,  vh2 + (size_t)(kb+key)*(HDIM/2) + c8*4);
        }
        if (tid < 128) {
            int key = tid >> 1, c2 = tid & 1;
            cp16(base + KBUFB + VBUFB + key*SSTRB + c2*16,
                 ksph + (size_t)(kb+key)*(SDIM/2) + c2*4);
        }
    };

    const int nTiles = (q0 + AQT) / AKT;
    issue_tile(0, 0);
    asm volatile("cp.async.commit_group;");

    for (int t = 0; t < nTiles; t++) {
        const int kb = t*AKT;
        const int buf = t & 1;
        __syncthreads();
        if (t + 1 < nTiles) issue_tile(kb + AKT, buf ^ 1);
        asm volatile("cp.async.commit_group;");
        asm volatile("cp.async.wait_group 1;" ::: "memory");
        __syncthreads();

        if (kb > q0w + 15) continue;

        const unsigned kBase  = shbase + buf*ABUFB;
        const unsigned vBase  = kBase + KBUFB;
        const unsigned spBase = kBase + KBUFB + VBUFB;

        // ---- 4 independent 16-key slices: QK -> gate -> PV, s regs die per slice ----
        #pragma unroll
        for (int g2 = 0; g2 < 4; g2++) {
            float s0[4] = {0.f,0.f,0.f,0.f}, s1[4] = {0.f,0.f,0.f,0.f};

            // QK for keys [kb+g2*16, kb+g2*16+16)
            #pragma unroll
            for (int kt = 0; kt < 4; kt++) {
                uint4 bb = ldsm4(kBase + (g2*16 + kRow)*KSTRB + (kt*16 + kCol)*2);
                mma_f16(s0[0], s0[1], s0[2], s0[3],
                        qa[kt][0], qa[kt][1], qa[kt][2], qa[kt][3], bb.x, bb.y);
                mma_f16(s1[0], s1[1], s1[2], s1[3],
                        qa[kt][0], qa[kt][1], qa[kt][2], qa[kt][3], bb.z, bb.w);
            }

            // gate + mask + unnormalized exp
            {
                float sp0[4] = {0.f,0.f,0.f,0.f}, sp1[4] = {0.f,0.f,0.f,0.f};
                uint4 bb = ldsm4(spBase + (g2*16 + kRow)*SSTRB + kCol*2);
                mma_f16(sp0[0], sp0[1], sp0[2], sp0[3],
                        qsa[0], qsa[1], qsa[2], qsa[3], bb.x, bb.y);
                mma_f16(sp1[0], sp1[1], sp1[2], sp1[3],
                        qsa[0], qsa[1], qsa[2], qsa[3], bb.z, bb.w);

                #pragma unroll
                for (int j = 0; j < 4; j++) {
                    {
                        int key = kb + g2*16 + 2*t4 + (j & 1);
                        int row = (j >= 2) ? qr1 : qr0;
                        float gf = fmaf(0.5f, tanhf_a(sp0[j] * 0.125f), 0.5f);
                        float p  = (key > row) ? 0.f : ex2f(s0[j] * C_QK * gf);
                        s0[j] = p;
                        if (j >= 2) l1 += p; else l0 += p;
                    }
                    {
                        int key = kb + g2*16 + 8 + 2*t4 + (j & 1);
                        int row = (j >= 2) ? qr1 : qr0;
                        float gf = fmaf(0.5f, tanhf_a(sp1[j] * 0.125f), 0.5f);
                        float p  = (key > row) ? 0.f : ex2f(s1[j] * C_QK * gf);
                        s1[j] = p;
                        if (j >= 2) l1 += p; else l0 += p;
                    }
                }
            }

            // PV for this slice (k16 step = g2)
            unsigned a0 = packh2(s0[0], s0[1]);
            unsigned a1 = packh2(s0[2], s0[3]);
            unsigned a2 = packh2(s1[0], s1[1]);
            unsigned a3 = packh2(s1[2], s1[3]);
            #pragma unroll
            for (int dnp = 0; dnp < 4; dnp++) {
                uint4 bb = ldsm4t(vBase + (g2*16 + vRow)*KSTRB + (dnp*16 + vCol)*2);
                mma_f16(O[2*dnp  ][0], O[2*dnp  ][1], O[2*dnp  ][2], O[2*dnp  ][3],
                        a0, a1, a2, a3, bb.x, bb.y);
                mma_f16(O[2*dnp+1][0], O[2*dnp+1][1], O[2*dnp+1][2], O[2*dnp+1][3],
                        a0, a1, a2, a3, bb.z, bb.w);
            }
        }
    }

    // epilogue
    #pragma unroll
    for (int off = 1; off < 4; off <<= 1) {
        l0 += __shfl_xor_sync(0xffffffffu, l0, off);
        l1 += __shfl_xor_sync(0xffffffffu, l1, off);
    }
    float inv0 = rcpf(l0), inv1 = rcpf(l1);
    #pragma unroll
    for (int dn = 0; dn < 8; dn++) {
        int col2 = (h*HDIM + dn*8 + 2*t4) >> 1;
        g_atth[((size_t)b*SS + qr0)*(DD/2) + col2] = packh2(O[dn][0]*inv0, O[dn][1]*inv0);
        g_atth[((size_t)b*SS + qr1)*(DD/2) + col2] = packh2(O[dn][2]*inv1, O[dn][3]*inv1);
    }
}

// ---------------- launch ----------------
extern "C" void kernel_launch(void* const* d_in, const int* in_sizes, int n_in,
                              void* d_out, int out_size)
{
    (void)in_sizes; (void)n_in; (void)out_size;
    const float* x  = (const float*)d_in[0];
    const float* Wq = (const float*)d_in[1];
    const float* Wk = (const float*)d_in[2];
    const float* Wv = (const float*)d_in[3];
    const float* Wo = (const float*)d_in[4];
    const float* bo = (const float*)d_in[5];
    const float* Ws = (const float*)d_in[6];
    const float* bs = (const float*)d_in[7];
    float* out = (float*)d_out;

    float *qlin, *klin, *vlin;
    unsigned *xh, *wqh, *wkh, *wvh, *woh, *atth;
    cudaGetSymbolAddress((void**)&qlin, g_qlin);
    cudaGetSymbolAddress((void**)&klin, g_klin);
    cudaGetSymbolAddress((void**)&vlin, g_vlin);
    cudaGetSymbolAddress((void**)&xh,   g_xh);
    cudaGetSymbolAddress((void**)&wqh,  g_wqh);
    cudaGetSymbolAddress((void**)&wkh,  g_wkh);
    cudaGetSymbolAddress((void**)&wvh,  g_wvh);
    cudaGetSymbolAddress((void**)&woh,  g_woh);
    cudaGetSymbolAddress((void**)&atth, g_atth);

    const int M = BB*SS;   // 4096

    static bool attr_set = false;
    if (!attr_set) {
        cudaFuncSetAttribute(gemm3h, cudaFuncAttributeMaxDynamicSharedMemorySize, GSMEM);
        cudaFuncSetAttribute(attn_mma_kernel, cudaFuncAttributeMaxDynamicSharedMemorySize, ASMEM);
        attr_set = true;
    }

    prep_kernel<<<PREP_BLOCKS, 256>>>(x, Wq, Wk, Wv, Wo);

    gemm3h<<<dim3(12, M/TBM), 256, GSMEM>>>(xh,
                                    wqh, qlin, 8, DD,
                                    wkh, klin, 2, HKV*HDIM,
                                    wvh, vlin, 2, HKV*HDIM,
                                    nullptr, DD);

    rope_sp_all<<<(BB*SS*(HH+HKV) + 255)/256, 256>>>(Ws, bs);

    attn_mma_kernel<<<dim3(SS/AQT, HH, BB), 256, ASMEM>>>();

    gemm3h<<<dim3(8, M/TBM), 256, GSMEM>>>(atth,
                                    woh, out, 8, DD,
                                    nullptr, nullptr, 0, 0,
                                    nullptr, nullptr, 0, 0,
                                    bo, DD);
}

// round 16
// speedup vs baseline: 1.8152x; 1.1842x over previous
#include <cuda_runtime.h>
#include <cuda_bf16.h>
#include <cuda_fp16.h>
#include <math.h>

#define BB 2
#define SS 2048
#define DD 1024
#define HH 16
#define HKV 4
#define HDIM 64
#define SDIM 16

// ---------------- scratch (device globals; no allocation) ----------------
__device__ float    g_qlin[BB*SS*DD];
__device__ float    g_klin[BB*SS*HKV*HDIM];
__device__ float    g_vlin[BB*SS*HKV*HDIM];
__device__ unsigned g_qh  [BB*HH*SS*HDIM/2];
__device__ unsigned g_qsph[BB*HH*SS*SDIM/2];
__device__ unsigned g_kh  [BB*HKV*SS*HDIM/2];
__device__ unsigned g_ksph[BB*HKV*SS*SDIM/2];
__device__ unsigned g_vh  [BB*HKV*SS*HDIM/2];
__device__ unsigned g_atth[BB*SS*DD/2];
__device__ unsigned g_xh  [BB*SS*DD/2];
__device__ unsigned g_wqh [DD*DD/2];
__device__ unsigned g_wkh [HKV*HDIM*DD/2];
__device__ unsigned g_wvh [HKV*HDIM*DD/2];
__device__ unsigned g_woh [DD*DD/2];
__device__ float    g_cosT[SS*(HDIM/2)];
__device__ float    g_sinT[SS*(HDIM/2)];

// ---------------- common helpers ----------------
__device__ __forceinline__ float rcpf(float x) {
    float r; asm("rcp.approx.f32 %0, %1;" : "=f"(r) : "f"(x)); return r;
}
__device__ __forceinline__ unsigned packh2(float a, float b) {
    unsigned r; asm("cvt.rn.f16x2.f32 %0, %1, %2;" : "=r"(r) : "f"(b), "f"(a)); return r;
}
__device__ __forceinline__ unsigned h2mul(unsigned a, unsigned b) {
    unsigned r; asm("mul.rn.f16x2 %0, %1, %2;" : "=r"(r) : "r"(a), "r"(b)); return r;
}
__device__ __forceinline__ unsigned h2fma(unsigned a, unsigned b, unsigned c) {
    unsigned r; asm("fma.rn.f16x2 %0, %1, %2, %3;" : "=r"(r) : "r"(a), "r"(b), "r"(c)); return r;
}
__device__ __forceinline__ unsigned h2tanh(unsigned a) {
    unsigned r; asm("tanh.approx.f16x2 %0, %1;" : "=r"(r) : "r"(a)); return r;
}
__device__ __forceinline__ unsigned h2ex2(unsigned a) {
    unsigned r; asm("ex2.approx.f16x2 %0, %1;" : "=r"(r) : "r"(a)); return r;
}
__device__ __forceinline__ void mma_f16(float& d0, float& d1, float& d2, float& d3,
                                        unsigned a0, unsigned a1, unsigned a2, unsigned a3,
                                        unsigned b0, unsigned b1) {
    asm volatile(
        "mma.sync.aligned.m16n8k16.row.col.f32.f16.f16.f32 "
        "{%0,%1,%2,%3},{%4,%5,%6,%7},{%8,%9},{%0,%1,%2,%3};"
        : "+f"(d0), "+f"(d1), "+f"(d2), "+f"(d3)
        : "r"(a0), "r"(a1), "r"(a2), "r"(a3), "r"(b0), "r"(b1));
}
__device__ __forceinline__ unsigned smem_u32(const void* p) {
    return (unsigned)__cvta_generic_to_shared(p);
}
__device__ __forceinline__ void cp16(unsigned dst, const void* src) {
    asm volatile("cp.async.cg.shared.global [%0], [%1], 16;" :: "r"(dst), "l"(src));
}
__device__ __forceinline__ uint4 ldsm4(unsigned addr) {
    uint4 r;
    asm volatile("ldmatrix.sync.aligned.m8n8.x4.shared.b16 {%0,%1,%2,%3}, [%4];"
                 : "=r"(r.x), "=r"(r.y), "=r"(r.z), "=r"(r.w) : "r"(addr));
    return r;
}
__device__ __forceinline__ uint4 ldsm4t(unsigned addr) {
    uint4 r;
    asm volatile("ldmatrix.sync.aligned.m8n8.x4.trans.shared.b16 {%0,%1,%2,%3}, [%4];"
                 : "=r"(r.x), "=r"(r.y), "=r"(r.z), "=r"(r.w) : "r"(addr));
    return r;
}

// ---------------- fused prologue: rope table + all fp16 conversions ----------------
#define PREP_BLOCKS 3584

__device__ __forceinline__ void cvt_seg_h(const float* __restrict__ in,
                                          unsigned* __restrict__ out, int blk) {
    int i = blk*256 + threadIdx.x;
    float4 f0 = ((const float4*)in)[2*i];
    float4 f1 = ((const float4*)in)[2*i+1];
    uint4 u;
    u.x = packh2(f0.x, f0.y); u.y = packh2(f0.z, f0.w);
    u.z = packh2(f1.x, f1.y); u.w = packh2(f1.z, f1.w);
    ((uint4*)out)[i] = u;
}

__global__ void prep_kernel(const float* __restrict__ x,
                            const float* __restrict__ Wq,
                            const float* __restrict__ Wk,
                            const float* __restrict__ Wv,
                            const float* __restrict__ Wo)
{
    int bx = blockIdx.x;
    if (bx < 2048)      { cvt_seg_h(x,  g_xh,  bx); }
    else if (bx < 2560) { cvt_seg_h(Wq, g_wqh, bx - 2048); }
    else if (bx < 2688) { cvt_seg_h(Wk, g_wkh, bx - 2560); }
    else if (bx < 2816) { cvt_seg_h(Wv, g_wvh, bx - 2688); }
    else if (bx < 3328) { cvt_seg_h(Wo, g_woh, bx - 2816); }
    else {
        int idx = (bx - 3328)*256 + threadIdx.x;
        int s = idx / (HDIM/2), i = idx % (HDIM/2);
        float thf = (float)pow(10000.0, -(double)i / (double)(HDIM/2));
        float ff  = (float)s * thf;
        g_cosT[idx] = (float)cos((double)ff);
        g_sinT[idx] = (float)sin((double)ff);
    }
}

// ================= FP16 m16n8k16 GEMM (unchanged) =================
#define TBM 128
#define TBN 128
#define RSTB 80
#define STG 3
#define GSMEM (STG*(TBM+TBN)*RSTB)

__global__ void __launch_bounds__(256) gemm3h(
    const unsigned* __restrict__ A,
    const unsigned* __restrict__ W0, float* __restrict__ C0, int nx0, int N0,
    const unsigned* __restrict__ W1, float* __restrict__ C1, int nx1, int N1,
    const unsigned* __restrict__ W2, float* __restrict__ C2, int nx2, int N2,
    const float* __restrict__ bias, int K)
{
    extern __shared__ unsigned sh[];
    const int tid = threadIdx.x;
    const int w = tid >> 5, lane = tid & 31;
    const int gid = lane >> 2, t4 = lane & 3;
    const int wm = w & 1, wn = w >> 1;
    const int row0 = blockIdx.y*TBM;
    const int K2 = K >> 1;

    const unsigned* Wp; float* Cp; int N, cb;
    int bx = blockIdx.x;
    if (bx < nx0)            { Wp = W0; Cp = C0; N = N0; cb = bx; }
    else if (bx < nx0 + nx1) { Wp = W1; Cp = C1; N = N1; cb = bx - nx0; }
    else                     { Wp = W2; Cp = C2; N = N2; cb = bx - nx0 - nx1; }
    const int col0 = cb*TBN;

    const unsigned* Aptr = A  + (size_t)row0*K2;
    const unsigned* Wptr = Wp + (size_t)col0*K2;

    const unsigned asA = smem_u32(sh);
    const unsigned asB = asA + STG*TBM*RSTB;

    const int cr = tid >> 1, cc16 = tid & 1;

    const int kRow = ((lane >> 4) << 3) | (lane & 7);
    const int kCol = ((lane >> 3) & 1) << 3;
    int aoffB[4], boffB[2];
    #pragma unroll
    for (int mt = 0; mt < 4; mt++)
        aoffB[mt] = (wm*64 + mt*16 + (lane & 15))*RSTB + ((lane >> 4) << 4);
    #pragma unroll
    for (int np = 0; np < 2; np++)
        boffB[np] = (wn*32 + np*16 + kRow)*RSTB + kCol*2;

    #pragma unroll
    for (int s = 0; s < STG-1; s++) {
        int kh2 = s*16;
        #pragma unroll
        for (int c = 0; c < 2; c++) {
            int c16 = cc16*2 + c;
            cp16(asA + s*(TBM*RSTB) + cr*RSTB + c16*16, Aptr + (size_t)cr*K2 + kh2 + c16*4);
            cp16(asB + s*(TBN*RSTB) + cr*RSTB + c16*16, Wptr + (size_t)cr*K2 + kh2 + c16*4);
        }
        asm volatile("cp.async.commit_group;");
    }

    float acc[4][4][4];
    #pragma unroll
    for (int mt = 0; mt < 4; mt++)
        #pragma unroll
        for (int nt = 0; nt < 4; nt++)
            #pragma unroll
            for (int j = 0; j < 4; j++) acc[mt][nt][j] = 0.f;

    const int T = K / 32;
    int st = 0, si = STG - 1;
    for (int t = 0; t < T; t++) {
        asm volatile("cp.async.wait_group 1;" ::: "memory");
        __syncthreads();

        if (t + STG - 1 < T) {
            int kh2 = (t + STG - 1)*16;
            #pragma unroll
            for (int c = 0; c < 2; c++) {
                int c16 = cc16*2 + c;
                cp16(asA + si*(TBM*RSTB) + cr*RSTB + c16*16, Aptr + (size_t)cr*K2 + kh2 + c16*4);
                cp16(asB + si*(TBN*RSTB) + cr*RSTB + c16*16, Wptr + (size_t)cr*K2 + kh2 + c16*4);
            }
        }
        asm volatile("cp.async.commit_group;");

        const unsigned aStg = asA + st*(TBM*RSTB);
        const unsigned bStg = asB + st*(TBN*RSTB);
        #pragma unroll
        for (int k16 = 0; k16 < 2; k16++) {
            const int kb = k16*32;
            uint4 av[4], bv[2];
            #pragma unroll
            for (int mt = 0; mt < 4; mt++) av[mt] = ldsm4(aStg + aoffB[mt] + kb);
            #pragma unroll
            for (int np = 0; np < 2; np++) bv[np] = ldsm4(bStg + boffB[np] + kb);
            #pragma unroll
            for (int np = 0; np < 2; np++) {
                #pragma unroll
                for (int mt = 0; mt < 4; mt++) {
                    mma_f16(acc[mt][2*np  ][0], acc[mt][2*np  ][1], acc[mt][2*np  ][2], acc[mt][2*np  ][3],
                            av[mt].x, av[mt].y, av[mt].z, av[mt].w, bv[np].x, bv[np].y);
                    mma_f16(acc[mt][2*np+1][0], acc[mt][2*np+1][1], acc[mt][2*np+1][2], acc[mt][2*np+1][3],
                            av[mt].x, av[mt].y, av[mt].z, av[mt].w, bv[np].z, bv[np].w);
                }
            }
        }
        st = (st + 1 == STG) ? 0 : st + 1;
        si = (si + 1 == STG) ? 0 : si + 1;
    }

    #pragma unroll
    for (int mt = 0; mt < 4; mt++) {
        int r = row0 + wm*64 + mt*16 + gid;
        #pragma unroll
        for (int nt = 0; nt < 4; nt++) {
            int c = col0 + wn*32 + nt*8 + 2*t4;
            float bv0 = bias ? bias[c]   : 0.f;
            float bv1 = bias ? bias[c+1] : 0.f;
            *(float2*)&Cp[(size_t)r*N + c]     = make_float2(acc[mt][nt][0]+bv0, acc[mt][nt][1]+bv1);
            *(float2*)&Cp[(size_t)(r+8)*N + c] = make_float2(acc[mt][nt][2]+bv0, acc[mt][nt][3]+bv1);
        }
    }
}

// ---------------- fused RoPE + sparsity projection -> fp16 outputs ----------------
__global__ void rope_sp_all(const float* __restrict__ Ws,
                            const float* __restrict__ bs)
{
    __shared__ float WsS[SDIM*HDIM];
    __shared__ float bsS[SDIM];
    for (int i = threadIdx.x; i < SDIM*HDIM; i += blockDim.x) WsS[i] = Ws[i];
    if (threadIdx.x < SDIM) bsS[threadIdx.x] = bs[threadIdx.x];
    __syncthreads();

    const int NQ = BB*SS*HH;
    int gidx = blockIdx.x*blockDim.x + threadIdx.x;

    const float* lin; unsigned *obuf, *spbuf;
    bool doV = false;
    int b, s, h, NH;
    if (gidx < NQ) {
        NH = HH;
        h = gidx % NH; s = (gidx / NH) % SS; b = gidx / (NH*SS);
        lin = g_qlin; obuf = g_qh; spbuf = g_qsph;
    } else {
        int idx = gidx - NQ;
        if (idx >= BB*SS*HKV) return;
        NH = HKV;
        s = idx % SS; h = (idx / SS) % HKV; b = idx / (SS*HKV);
        lin = g_klin; obuf = g_kh; spbuf = g_ksph;
        doV = true;
    }

    const float4* src = (const float4*)(lin + ((size_t)(b*SS + s)*NH + h)*HDIM);
    float v[HDIM];
    #pragma unroll
    for (int t = 0; t < HDIM/4; t++) ((float4*)v)[t] = src[t];

    #pragma unroll
    for (int i = 0; i < HDIM/2; i++) {
        float c  = g_cosT[s*(HDIM/2)+i];
        float sn = g_sinT[s*(HDIM/2)+i];
        float a  = v[i], bpart = v[i+HDIM/2];
        v[i]        = a*c - bpart*sn;
        v[i+HDIM/2] = bpart*c + a*sn;
    }

    unsigned hh[HDIM/2];
    #pragma unroll
    for (int d = 0; d < HDIM/2; d++) hh[d] = packh2(v[2*d], v[2*d+1]);
    unsigned* dst = obuf + (((size_t)b*NH + h)*SS + s)*(HDIM/2);
    #pragma unroll
    for (int t = 0; t < HDIM/8; t++) ((uint4*)dst)[t] = ((uint4*)hh)[t];

    float sp[SDIM];
    #pragma unroll
    for (int j = 0; j < SDIM; j++) {
        float acc = bsS[j];
        #pragma unroll
        for (int d = 0; d < HDIM; d++) acc += WsS[j*HDIM + d] * v[d];
        sp[j] = acc;
    }
    unsigned* spd = spbuf + (((size_t)b*NH + h)*SS + s)*(SDIM/2);
    #pragma unroll
    for (int j = 0; j < SDIM/2; j++) spd[j] = packh2(sp[2*j], sp[2*j+1]);

    if (doV) {
        const float* vsrc = g_vlin + ((size_t)(b*SS + s)*NH + h)*HDIM;
        unsigned vv[HDIM/2];
        #pragma unroll
        for (int d = 0; d < HDIM/2; d++) vv[d] = packh2(vsrc[2*d], vsrc[2*d+1]);
        unsigned* vdst = g_vh + (((size_t)b*HKV + h)*SS + s)*(HDIM/2);
        #pragma unroll
        for (int t = 0; t < HDIM/8; t++) ((uint4*)vdst)[t] = ((uint4*)vv)[t];
    }
}

// ================= FP16 attention: h2 gate pipeline + ones-column l =================
#define AQT 128
#define AKT 64
#define KSTRB 144
#define VSTRB 176     // V rows padded: cols 64..87, col 64 = 1.0 (ones column for l)
#define SSTRB 48
#define KBUFB (AKT*KSTRB)
#define VBUFB (AKT*VSTRB)
#define SBUFB (AKT*SSTRB)
#define ABUFB (KBUFB+VBUFB+SBUFB)
#define ASMEM (2*ABUFB)

#define H0125 0x30003000u   // half2 {0.125, 0.125}
#define H05   0x38003800u   // half2 {0.5, 0.5}
#define HCQK  0x31C531C5u   // half2 {0.18034, 0.18034} = 0.125*log2(e)
#define HONE  0x3C00u

__global__ void __launch_bounds__(256, 2) attn_mma_kernel()
{
    extern __shared__ unsigned ash[];

    const int b = blockIdx.z, h = blockIdx.y;
    const int hkv = h >> 2;
    const int q0 = (gridDim.x - 1 - blockIdx.x) * AQT;
    const int tid = threadIdx.x;
    const int w = tid >> 5, lane = tid & 31;
    const int gid = lane >> 2, t4 = lane & 3;

    const int q0w = q0 + w*16;
    const int qr0 = q0w + gid;
    const int qr1 = qr0 + 8;

    const unsigned* qh2  = g_qh  + ((size_t)b*HH  + h  )*SS*(HDIM/2);
    const unsigned* qsph = g_qsph+ ((size_t)b*HH  + h  )*SS*(SDIM/2);
    const unsigned* kh2  = g_kh  + ((size_t)b*HKV + hkv)*SS*(HDIM/2);
    const unsigned* ksph = g_ksph+ ((size_t)b*HKV + hkv)*SS*(SDIM/2);
    const unsigned* vh2  = g_vh  + ((size_t)b*HKV + hkv)*SS*(HDIM/2);

    const unsigned shbase = smem_u32(ash);

    const int kRow = ((lane >> 4) << 3) | (lane & 7);
    const int kCol = ((lane >> 3) & 1) << 3;
    const int vRow = (((lane >> 3) & 1) << 3) | (lane & 7);
    const int vCol = (lane >> 4) << 3;

    unsigned qa[4][4], qsa[4];
    #pragma unroll
    for (int kt = 0; kt < 4; kt++) {
        qa[kt][0] = qh2[(size_t)qr0*(HDIM/2) + kt*8 + t4];
        qa[kt][1] = qh2[(size_t)qr1*(HDIM/2) + kt*8 + t4];
        qa[kt][2] = qh2[(size_t)qr0*(HDIM/2) + kt*8 + t4 + 4];
        qa[kt][3] = qh2[(size_t)qr1*(HDIM/2) + kt*8 + t4 + 4];
    }
    qsa[0] = qsph[(size_t)qr0*(SDIM/2) + t4];
    qsa[1] = qsph[(size_t)qr1*(SDIM/2) + t4];
    qsa[2] = qsph[(size_t)qr0*(SDIM/2) + t4 + 4];
    qsa[3] = qsph[(size_t)qr1*(SDIM/2) + t4 + 4];

    float O[8][4];
    #pragma unroll
    for (int dn = 0; dn < 8; dn++)
        #pragma unroll
        for (int j = 0; j < 4; j++) O[dn][j] = 0.f;
    float Ol[4] = {0.f, 0.f, 0.f, 0.f};   // ones-column accumulator (col 64 = l)

    auto issue_tile = [&](int kb, int buf) {
        unsigned base = shbase + buf*ABUFB;
        #pragma unroll
        for (int c = 0; c < 2; c++) {
            int i = tid + c*256;
            int key = i >> 3, c8 = i & 7;
            cp16(base + key*KSTRB + c8*16,          kh2 + (size_t)(kb+key)*(HDIM/2) + c8*4);
            cp16(base + KBUFB + key*VSTRB + c8*16,  vh2 + (size_t)(kb+key)*(HDIM/2) + c8*4);
        }
        if (tid < 128) {
            int key = tid >> 1, c2 = tid & 1;
            cp16(base + KBUFB + VBUFB + key*SSTRB + c2*16,
                 ksph + (size_t)(kb+key)*(SDIM/2) + c2*4);
        }
    };

    const int nTiles = (q0 + AQT) / AKT;
    issue_tile(0, 0);
    asm volatile("cp.async.commit_group;");

    // init V pad (cols 64..87): col 64 = 1.0, rest 0 — both buffers
    for (int k = tid; k < 2*64*12; k += 256) {
        int buf = (k >= 64*12) ? 1 : 0;
        int kk = k - buf*64*12;
        int r = kk / 12, c = kk % 12;
        unsigned val = (c == 0) ? 0x00003C00u : 0u;
        *(unsigned*)((char*)ash + buf*ABUFB + KBUFB + r*VSTRB + 128 + c*4) = val;
    }

    for (int t = 0; t < nTiles; t++) {
        const int kb = t*AKT;
        const int buf = t & 1;
        __syncthreads();
        if (t + 1 < nTiles) issue_tile(kb + AKT, buf ^ 1);
        asm volatile("cp.async.commit_group;");
        asm volatile("cp.async.wait_group 1;" ::: "memory");
        __syncthreads();

        if (kb > q0w + 15) continue;

        const unsigned kBase  = shbase + buf*ABUFB;
        const unsigned vBase  = kBase + KBUFB;
        const unsigned spBase = kBase + KBUFB + VBUFB;
        const bool needMask = (kb + AKT - 1 > q0w);

        #pragma unroll
        for (int g2 = 0; g2 < 4; g2++) {
            float s0[4] = {0.f,0.f,0.f,0.f}, s1[4] = {0.f,0.f,0.f,0.f};

            #pragma unroll
            for (int kt = 0; kt < 4; kt++) {
                uint4 bb = ldsm4(kBase + (g2*16 + kRow)*KSTRB + (kt*16 + kCol)*2);
                mma_f16(s0[0], s0[1], s0[2], s0[3],
                        qa[kt][0], qa[kt][1], qa[kt][2], qa[kt][3], bb.x, bb.y);
                mma_f16(s1[0], s1[1], s1[2], s1[3],
                        qa[kt][0], qa[kt][1], qa[kt][2], qa[kt][3], bb.z, bb.w);
            }

            float sp0[4] = {0.f,0.f,0.f,0.f}, sp1[4] = {0.f,0.f,0.f,0.f};
            {
                uint4 bb = ldsm4(spBase + (g2*16 + kRow)*SSTRB + kCol*2);
                mma_f16(sp0[0], sp0[1], sp0[2], sp0[3],
                        qsa[0], qsa[1], qsa[2], qsa[3], bb.x, bb.y);
                mma_f16(sp1[0], sp1[1], sp1[2], sp1[3],
                        qsa[0], qsa[1], qsa[2], qsa[3], bb.z, bb.w);
            }

            // pack to half2: a0 = row qr0 keys(+0,+1); a1 = row qr1; a2/a3 = keys+8
            unsigned hs[4], hsp[4];
            hs[0] = packh2(s0[0], s0[1]);  hs[1] = packh2(s0[2], s0[3]);
            hs[2] = packh2(s1[0], s1[1]);  hs[3] = packh2(s1[2], s1[3]);
            hsp[0] = packh2(sp0[0], sp0[1]); hsp[1] = packh2(sp0[2], sp0[3]);
            hsp[2] = packh2(sp1[0], sp1[1]); hsp[3] = packh2(sp1[2], sp1[3]);

            unsigned p[4];
            #pragma unroll
            for (int i = 0; i < 4; i++) {
                unsigned g = h2fma(h2tanh(h2mul(hsp[i], H0125)), H05, H05);
                p[i] = h2ex2(h2mul(h2mul(hs[i], HCQK), g));
            }

            if (needMask) {
                int k0 = kb + g2*16 + 2*t4;      // keys for pairs 0,1
                int k8 = k0 + 8;                 // keys for pairs 2,3
                unsigned m0 = (k0 <= qr0 ? HONE : 0u) | (k0+1 <= qr0 ? (HONE<<16) : 0u);
                unsigned m1 = (k0 <= qr1 ? HONE : 0u) | (k0+1 <= qr1 ? (HONE<<16) : 0u);
                unsigned m2 = (k8 <= qr0 ? HONE : 0u) | (k8+1 <= qr0 ? (HONE<<16) : 0u);
                unsigned m3 = (k8 <= qr1 ? HONE : 0u) | (k8+1 <= qr1 ? (HONE<<16) : 0u);
                p[0] = h2mul(p[0], m0); p[1] = h2mul(p[1], m1);
                p[2] = h2mul(p[2], m2); p[3] = h2mul(p[3], m3);
            }

            // PV (+ ones column for l)
            #pragma unroll
            for (int dnp = 0; dnp < 4; dnp++) {
                uint4 bb = ldsm4t(vBase + (g2*16 + vRow)*VSTRB + (dnp*16 + vCol)*2);
                mma_f16(O[2*dnp  ][0], O[2*dnp  ][1], O[2*dnp  ][2], O[2*dnp  ][3],
                        p[0], p[1], p[2], p[3], bb.x, bb.y);
                mma_f16(O[2*dnp+1][0], O[2*dnp+1][1], O[2*dnp+1][2], O[2*dnp+1][3],
                        p[0], p[1], p[2], p[3], bb.z, bb.w);
            }
            {
                uint4 bb = ldsm4t(vBase + (g2*16 + vRow)*VSTRB + (4*16 + vCol)*2);
                mma_f16(Ol[0], Ol[1], Ol[2], Ol[3],
                        p[0], p[1], p[2], p[3], bb.x, bb.y);
            }
        }
    }

    // epilogue: l lives in col 64 (t4==0 lanes); broadcast within quad
    float lsum0 = __shfl_sync(0xffffffffu, Ol[0], lane & ~3);
    float lsum1 = __shfl_sync(0xffffffffu, Ol[2], lane & ~3);
    float inv0 = rcpf(lsum0), inv1 = rcpf(lsum1);
    #pragma unroll
    for (int dn = 0; dn < 8; dn++) {
        int col2 = (h*HDIM + dn*8 + 2*t4) >> 1;
        g_atth[((size_t)b*SS + qr0)*(DD/2) + col2] = packh2(O[dn][0]*inv0, O[dn][1]*inv0);
        g_atth[((size_t)b*SS + qr1)*(DD/2) + col2] = packh2(O[dn][2]*inv1, O[dn][3]*inv1);
    }
}

// ---------------- launch ----------------
extern "C" void kernel_launch(void* const* d_in, const int* in_sizes, int n_in,
                              void* d_out, int out_size)
{
    (void)in_sizes; (void)n_in; (void)out_size;
    const float* x  = (const float*)d_in[0];
    const float* Wq = (const float*)d_in[1];
    const float* Wk = (const float*)d_in[2];
    const float* Wv = (const float*)d_in[3];
    const float* Wo = (const float*)d_in[4];
    const float* bo = (const float*)d_in[5];
    const float* Ws = (const float*)d_in[6];
    const float* bs = (const float*)d_in[7];
    float* out = (float*)d_out;

    float *qlin, *klin, *vlin;
    unsigned *xh, *wqh, *wkh, *wvh, *woh, *atth;
    cudaGetSymbolAddress((void**)&qlin, g_qlin);
    cudaGetSymbolAddress((void**)&klin, g_klin);
    cudaGetSymbolAddress((void**)&vlin, g_vlin);
    cudaGetSymbolAddress((void**)&xh,   g_xh);
    cudaGetSymbolAddress((void**)&wqh,  g_wqh);
    cudaGetSymbolAddress((void**)&wkh,  g_wkh);
    cudaGetSymbolAddress((void**)&wvh,  g_wvh);
    cudaGetSymbolAddress((void**)&woh,  g_woh);
    cudaGetSymbolAddress((void**)&atth, g_atth);

    const int M = BB*SS;   // 4096

    static bool attr_set = false;
    if (!attr_set) {
        cudaFuncSetAttribute(gemm3h, cudaFuncAttributeMaxDynamicSharedMemorySize, GSMEM);
        cudaFuncSetAttribute(attn_mma_kernel, cudaFuncAttributeMaxDynamicSharedMemorySize, ASMEM);
        attr_set = true;
    }

    prep_kernel<<<PREP_BLOCKS, 256>>>(x, Wq, Wk, Wv, Wo);

    gemm3h<<<dim3(12, M/TBM), 256, GSMEM>>>(xh,
                                    wqh, qlin, 8, DD,
                                    wkh, klin, 2, HKV*HDIM,
                                    wvh, vlin, 2, HKV*HDIM,
                                    nullptr, DD);

    rope_sp_all<<<(BB*SS*(HH+HKV) + 255)/256, 256>>>(Ws, bs);

    attn_mma_kernel<<<dim3(SS/AQT, HH, BB), 256, ASMEM>>>();

    gemm3h<<<dim3(8, M/TBM), 256, GSMEM>>>(atth,
                                    woh, out, 8, DD,
                                    nullptr, nullptr, 0, 0,
                                    nullptr, nullptr, 0, 0,
                                    bo, DD);
}

// round 17
// speedup vs baseline: 1.8237x; 1.0047x over previous
#include <cuda_runtime.h>
#include <cuda_bf16.h>
#include <cuda_fp16.h>
#include <math.h>

#define BB 2
#define SS 2048
#define DD 1024
#define HH 16
#define HKV 4
#define HDIM 64
#define SDIM 16

// ---------------- scratch (device globals; no allocation) ----------------
__device__ float    g_qlin[BB*SS*DD];
__device__ float    g_klin[BB*SS*HKV*HDIM];
__device__ float    g_vlin[BB*SS*HKV*HDIM];
__device__ unsigned g_qh  [BB*HH*SS*HDIM/2];
__device__ unsigned g_qsph[BB*HH*SS*SDIM/2];
__device__ unsigned g_kh  [BB*HKV*SS*HDIM/2];
__device__ unsigned g_ksph[BB*HKV*SS*SDIM/2];
__device__ unsigned g_vh  [BB*HKV*SS*HDIM/2];
__device__ unsigned g_atth[BB*SS*DD/2];
__device__ unsigned g_xh  [BB*SS*DD/2];
__device__ unsigned g_wqh [DD*DD/2];
__device__ unsigned g_wkh [HKV*HDIM*DD/2];
__device__ unsigned g_wvh [HKV*HDIM*DD/2];
__device__ unsigned g_woh [DD*DD/2];
__device__ float    g_cosT[SS*(HDIM/2)];
__device__ float    g_sinT[SS*(HDIM/2)];

// ---------------- common helpers ----------------
__device__ __forceinline__ float rcpf(float x) {
    float r; asm("rcp.approx.f32 %0, %1;" : "=f"(r) : "f"(x)); return r;
}
__device__ __forceinline__ unsigned packh2(float a, float b) {
    unsigned r; asm("cvt.rn.f16x2.f32 %0, %1, %2;" : "=r"(r) : "f"(b), "f"(a)); return r;
}
__device__ __forceinline__ unsigned h2mul(unsigned a, unsigned b) {
    unsigned r; asm("mul.rn.f16x2 %0, %1, %2;" : "=r"(r) : "r"(a), "r"(b)); return r;
}
__device__ __forceinline__ unsigned h2fma(unsigned a, unsigned b, unsigned c) {
    unsigned r; asm("fma.rn.f16x2 %0, %1, %2, %3;" : "=r"(r) : "r"(a), "r"(b), "r"(c)); return r;
}
__device__ __forceinline__ unsigned h2tanh(unsigned a) {
    unsigned r; asm("tanh.approx.f16x2 %0, %1;" : "=r"(r) : "r"(a)); return r;
}
__device__ __forceinline__ unsigned h2ex2(unsigned a) {
    unsigned r; asm("ex2.approx.f16x2 %0, %1;" : "=r"(r) : "r"(a)); return r;
}
__device__ __forceinline__ void mma_f16(float& d0, float& d1, float& d2, float& d3,
                                        unsigned a0, unsigned a1, unsigned a2, unsigned a3,
                                        unsigned b0, unsigned b1) {
    asm volatile(
        "mma.sync.aligned.m16n8k16.row.col.f32.f16.f16.f32 "
        "{%0,%1,%2,%3},{%4,%5,%6,%7},{%8,%9},{%0,%1,%2,%3};"
        : "+f"(d0), "+f"(d1), "+f"(d2), "+f"(d3)
        : "r"(a0), "r"(a1), "r"(a2), "r"(a3), "r"(b0), "r"(b1));
}
__device__ __forceinline__ unsigned smem_u32(const void* p) {
    return (unsigned)__cvta_generic_to_shared(p);
}
__device__ __forceinline__ void cp16(unsigned dst, const void* src) {
    asm volatile("cp.async.cg.shared.global [%0], [%1], 16;" :: "r"(dst), "l"(src));
}
__device__ __forceinline__ uint4 ldsm4(unsigned addr) {
    uint4 r;
    asm volatile("ldmatrix.sync.aligned.m8n8.x4.shared.b16 {%0,%1,%2,%3}, [%4];"
                 : "=r"(r.x), "=r"(r.y), "=r"(r.z), "=r"(r.w) : "r"(addr));
    return r;
}
__device__ __forceinline__ uint4 ldsm4t(unsigned addr) {
    uint4 r;
    asm volatile("ldmatrix.sync.aligned.m8n8.x4.trans.shared.b16 {%0,%1,%2,%3}, [%4];"
                 : "=r"(r.x), "=r"(r.y), "=r"(r.z), "=r"(r.w) : "r"(addr));
    return r;
}

// ---------------- fused prologue: rope table + all fp16 conversions ----------------
#define PREP_BLOCKS 3584

__device__ __forceinline__ void cvt_seg_h(const float* __restrict__ in,
                                          unsigned* __restrict__ out, int blk) {
    int i = blk*256 + threadIdx.x;
    float4 f0 = ((const float4*)in)[2*i];
    float4 f1 = ((const float4*)in)[2*i+1];
    uint4 u;
    u.x = packh2(f0.x, f0.y); u.y = packh2(f0.z, f0.w);
    u.z = packh2(f1.x, f1.y); u.w = packh2(f1.z, f1.w);
    ((uint4*)out)[i] = u;
}

__global__ void prep_kernel(const float* __restrict__ x,
                            const float* __restrict__ Wq,
                            const float* __restrict__ Wk,
                            const float* __restrict__ Wv,
                            const float* __restrict__ Wo)
{
    int bx = blockIdx.x;
    if (bx < 2048)      { cvt_seg_h(x,  g_xh,  bx); }
    else if (bx < 2560) { cvt_seg_h(Wq, g_wqh, bx - 2048); }
    else if (bx < 2688) { cvt_seg_h(Wk, g_wkh, bx - 2560); }
    else if (bx < 2816) { cvt_seg_h(Wv, g_wvh, bx - 2688); }
    else if (bx < 3328) { cvt_seg_h(Wo, g_woh, bx - 2816); }
    else {
        int idx = (bx - 3328)*256 + threadIdx.x;
        int s = idx / (HDIM/2), i = idx % (HDIM/2);
        float thf = (float)pow(10000.0, -(double)i / (double)(HDIM/2));
        float ff  = (float)s * thf;
        g_cosT[idx] = (float)cos((double)ff);
        g_sinT[idx] = (float)sin((double)ff);
    }
}

// ================= FP16 m16n8k16 GEMM: 4-stage cp.async pipeline =================
#define TBM 128
#define TBN 128
#define RSTB 80
#define STG 4
#define GSMEM (STG*(TBM+TBN)*RSTB)

__global__ void __launch_bounds__(256) gemm3h(
    const unsigned* __restrict__ A,
    const unsigned* __restrict__ W0, float* __restrict__ C0, int nx0, int N0,
    const unsigned* __restrict__ W1, float* __restrict__ C1, int nx1, int N1,
    const unsigned* __restrict__ W2, float* __restrict__ C2, int nx2, int N2,
    const float* __restrict__ bias, int K)
{
    extern __shared__ unsigned sh[];
    const int tid = threadIdx.x;
    const int w = tid >> 5, lane = tid & 31;
    const int gid = lane >> 2, t4 = lane & 3;
    const int wm = w & 1, wn = w >> 1;
    const int row0 = blockIdx.y*TBM;
    const int K2 = K >> 1;

    const unsigned* Wp; float* Cp; int N, cb;
    int bx = blockIdx.x;
    if (bx < nx0)            { Wp = W0; Cp = C0; N = N0; cb = bx; }
    else if (bx < nx0 + nx1) { Wp = W1; Cp = C1; N = N1; cb = bx - nx0; }
    else                     { Wp = W2; Cp = C2; N = N2; cb = bx - nx0 - nx1; }
    const int col0 = cb*TBN;

    const unsigned* Aptr = A  + (size_t)row0*K2;
    const unsigned* Wptr = Wp + (size_t)col0*K2;

    const unsigned asA = smem_u32(sh);
    const unsigned asB = asA + STG*TBM*RSTB;

    const int cr = tid >> 1, cc16 = tid & 1;

    const int kRow = ((lane >> 4) << 3) | (lane & 7);
    const int kCol = ((lane >> 3) & 1) << 3;
    int aoffB[4], boffB[2];
    #pragma unroll
    for (int mt = 0; mt < 4; mt++)
        aoffB[mt] = (wm*64 + mt*16 + (lane & 15))*RSTB + ((lane >> 4) << 4);
    #pragma unroll
    for (int np = 0; np < 2; np++)
        boffB[np] = (wn*32 + np*16 + kRow)*RSTB + kCol*2;

    #pragma unroll
    for (int s = 0; s < STG-1; s++) {
        int kh2 = s*16;
        #pragma unroll
        for (int c = 0; c < 2; c++) {
            int c16 = cc16*2 + c;
            cp16(asA + s*(TBM*RSTB) + cr*RSTB + c16*16, Aptr + (size_t)cr*K2 + kh2 + c16*4);
            cp16(asB + s*(TBN*RSTB) + cr*RSTB + c16*16, Wptr + (size_t)cr*K2 + kh2 + c16*4);
        }
        asm volatile("cp.async.commit_group;");
    }

    float acc[4][4][4];
    #pragma unroll
    for (int mt = 0; mt < 4; mt++)
        #pragma unroll
        for (int nt = 0; nt < 4; nt++)
            #pragma unroll
            for (int j = 0; j < 4; j++) acc[mt][nt][j] = 0.f;

    const int T = K / 32;
    int st = 0, si = STG - 1;
    for (int t = 0; t < T; t++) {
        asm volatile("cp.async.wait_group 2;" ::: "memory");
        __syncthreads();

        if (t + STG - 1 < T) {
            int kh2 = (t + STG - 1)*16;
            #pragma unroll
            for (int c = 0; c < 2; c++) {
                int c16 = cc16*2 + c;
                cp16(asA + si*(TBM*RSTB) + cr*RSTB + c16*16, Aptr + (size_t)cr*K2 + kh2 + c16*4);
                cp16(asB + si*(TBN*RSTB) + cr*RSTB + c16*16, Wptr + (size_t)cr*K2 + kh2 + c16*4);
            }
        }
        asm volatile("cp.async.commit_group;");

        const unsigned aStg = asA + st*(TBM*RSTB);
        const unsigned bStg = asB + st*(TBN*RSTB);
        #pragma unroll
        for (int k16 = 0; k16 < 2; k16++) {
            const int kb = k16*32;
            uint4 av[4], bv[2];
            #pragma unroll
            for (int mt = 0; mt < 4; mt++) av[mt] = ldsm4(aStg + aoffB[mt] + kb);
            #pragma unroll
            for (int np = 0; np < 2; np++) bv[np] = ldsm4(bStg + boffB[np] + kb);
            #pragma unroll
            for (int np = 0; np < 2; np++) {
                #pragma unroll
                for (int mt = 0; mt < 4; mt++) {
                    mma_f16(acc[mt][2*np  ][0], acc[mt][2*np  ][1], acc[mt][2*np  ][2], acc[mt][2*np  ][3],
                            av[mt].x, av[mt].y, av[mt].z, av[mt].w, bv[np].x, bv[np].y);
                    mma_f16(acc[mt][2*np+1][0], acc[mt][2*np+1][1], acc[mt][2*np+1][2], acc[mt][2*np+1][3],
                            av[mt].x, av[mt].y, av[mt].z, av[mt].w, bv[np].z, bv[np].w);
                }
            }
        }
        st = (st + 1 == STG) ? 0 : st + 1;
        si = (si + 1 == STG) ? 0 : si + 1;
    }

    #pragma unroll
    for (int mt = 0; mt < 4; mt++) {
        int r = row0 + wm*64 + mt*16 + gid;
        #pragma unroll
        for (int nt = 0; nt < 4; nt++) {
            int c = col0 + wn*32 + nt*8 + 2*t4;
            float bv0 = bias ? bias[c]   : 0.f;
            float bv1 = bias ? bias[c+1] : 0.f;
            *(float2*)&Cp[(size_t)r*N + c]     = make_float2(acc[mt][nt][0]+bv0, acc[mt][nt][1]+bv1);
            *(float2*)&Cp[(size_t)(r+8)*N + c] = make_float2(acc[mt][nt][2]+bv0, acc[mt][nt][3]+bv1);
        }
    }
}

// ---------------- fused RoPE + sparsity projection -> fp16 outputs ----------------
__global__ void rope_sp_all(const float* __restrict__ Ws,
                            const float* __restrict__ bs)
{
    __shared__ float WsS[SDIM*HDIM];
    __shared__ float bsS[SDIM];
    for (int i = threadIdx.x; i < SDIM*HDIM; i += blockDim.x) WsS[i] = Ws[i];
    if (threadIdx.x < SDIM) bsS[threadIdx.x] = bs[threadIdx.x];
    __syncthreads();

    const int NQ = BB*SS*HH;
    int gidx = blockIdx.x*blockDim.x + threadIdx.x;

    const float* lin; unsigned *obuf, *spbuf;
    bool doV = false;
    int b, s, h, NH;
    if (gidx < NQ) {
        NH = HH;
        h = gidx % NH; s = (gidx / NH) % SS; b = gidx / (NH*SS);
        lin = g_qlin; obuf = g_qh; spbuf = g_qsph;
    } else {
        int idx = gidx - NQ;
        if (idx >= BB*SS*HKV) return;
        NH = HKV;
        s = idx % SS; h = (idx / SS) % HKV; b = idx / (SS*HKV);
        lin = g_klin; obuf = g_kh; spbuf = g_ksph;
        doV = true;
    }

    const float4* src = (const float4*)(lin + ((size_t)(b*SS + s)*NH + h)*HDIM);
    float v[HDIM];
    #pragma unroll
    for (int t = 0; t < HDIM/4; t++) ((float4*)v)[t] = src[t];

    #pragma unroll
    for (int i = 0; i < HDIM/2; i++) {
        float c  = g_cosT[s*(HDIM/2)+i];
        float sn = g_sinT[s*(HDIM/2)+i];
        float a  = v[i], bpart = v[i+HDIM/2];
        v[i]        = a*c - bpart*sn;
        v[i+HDIM/2] = bpart*c + a*sn;
    }

    unsigned hh[HDIM/2];
    #pragma unroll
    for (int d = 0; d < HDIM/2; d++) hh[d] = packh2(v[2*d], v[2*d+1]);
    unsigned* dst = obuf + (((size_t)b*NH + h)*SS + s)*(HDIM/2);
    #pragma unroll
    for (int t = 0; t < HDIM/8; t++) ((uint4*)dst)[t] = ((uint4*)hh)[t];

    float sp[SDIM];
    #pragma unroll
    for (int j = 0; j < SDIM; j++) {
        float acc = bsS[j];
        #pragma unroll
        for (int d = 0; d < HDIM; d++) acc += WsS[j*HDIM + d] * v[d];
        sp[j] = acc;
    }
    unsigned* spd = spbuf + (((size_t)b*NH + h)*SS + s)*(SDIM/2);
    #pragma unroll
    for (int j = 0; j < SDIM/2; j++) spd[j] = packh2(sp[2*j], sp[2*j+1]);

    if (doV) {
        const float* vsrc = g_vlin + ((size_t)(b*SS + s)*NH + h)*HDIM;
        unsigned vv[HDIM/2];
        #pragma unroll
        for (int d = 0; d < HDIM/2; d++) vv[d] = packh2(vsrc[2*d], vsrc[2*d+1]);
        unsigned* vdst = g_vh + (((size_t)b*HKV + h)*SS + s)*(HDIM/2);
        #pragma unroll
        for (int t = 0; t < HDIM/8; t++) ((uint4*)vdst)[t] = ((uint4*)vv)[t];
    }
}

// ================= FP16 attention: triple-buffered, single sync per tile =================
#define AQT 128
#define AKT 64
#define KSTRB 144
#define VSTRB 176     // V rows padded: col 64 = 1.0 (ones column for l)
#define SSTRB 48
#define KBUFB (AKT*KSTRB)
#define VBUFB (AKT*VSTRB)
#define SBUFB (AKT*SSTRB)
#define ABUFB (KBUFB+VBUFB+SBUFB)
#define NBUF 3
#define ASMEM (NBUF*ABUFB)

#define H0125 0x30003000u
#define H05   0x38003800u
#define HCQK  0x31C531C5u   // 0.125*log2(e)
#define HONE  0x3C00u

__global__ void __launch_bounds__(256, 2) attn_mma_kernel()
{
    extern __shared__ unsigned ash[];

    const int b = blockIdx.z, h = blockIdx.y;
    const int hkv = h >> 2;
    const int q0 = (gridDim.x - 1 - blockIdx.x) * AQT;
    const int tid = threadIdx.x;
    const int w = tid >> 5, lane = tid & 31;
    const int gid = lane >> 2, t4 = lane & 3;

    const int q0w = q0 + w*16;
    const int qr0 = q0w + gid;
    const int qr1 = qr0 + 8;

    const unsigned* qh2  = g_qh  + ((size_t)b*HH  + h  )*SS*(HDIM/2);
    const unsigned* qsph = g_qsph+ ((size_t)b*HH  + h  )*SS*(SDIM/2);
    const unsigned* kh2  = g_kh  + ((size_t)b*HKV + hkv)*SS*(HDIM/2);
    const unsigned* ksph = g_ksph+ ((size_t)b*HKV + hkv)*SS*(SDIM/2);
    const unsigned* vh2  = g_vh  + ((size_t)b*HKV + hkv)*SS*(HDIM/2);

    const unsigned shbase = smem_u32(ash);

    const int kRow = ((lane >> 4) << 3) | (lane & 7);
    const int kCol = ((lane >> 3) & 1) << 3;
    const int vRow = (((lane >> 3) & 1) << 3) | (lane & 7);
    const int vCol = (lane >> 4) << 3;

    unsigned qa[4][4], qsa[4];
    #pragma unroll
    for (int kt = 0; kt < 4; kt++) {
        qa[kt][0] = qh2[(size_t)qr0*(HDIM/2) + kt*8 + t4];
        qa[kt][1] = qh2[(size_t)qr1*(HDIM/2) + kt*8 + t4];
        qa[kt][2] = qh2[(size_t)qr0*(HDIM/2) + kt*8 + t4 + 4];
        qa[kt][3] = qh2[(size_t)qr1*(HDIM/2) + kt*8 + t4 + 4];
    }
    qsa[0] = qsph[(size_t)qr0*(SDIM/2) + t4];
    qsa[1] = qsph[(size_t)qr1*(SDIM/2) + t4];
    qsa[2] = qsph[(size_t)qr0*(SDIM/2) + t4 + 4];
    qsa[3] = qsph[(size_t)qr1*(SDIM/2) + t4 + 4];

    float O[8][4];
    #pragma unroll
    for (int dn = 0; dn < 8; dn++)
        #pragma unroll
        for (int j = 0; j < 4; j++) O[dn][j] = 0.f;
    float Ol[4] = {0.f, 0.f, 0.f, 0.f};

    auto issue_tile = [&](int kb, int buf) {
        unsigned base = shbase + buf*ABUFB;
        #pragma unroll
        for (int c = 0; c < 2; c++) {
            int i = tid + c*256;
            int key = i >> 3, c8 = i & 7;
            cp16(base + key*KSTRB + c8*16,          kh2 + (size_t)(kb+key)*(HDIM/2) + c8*4);
            cp16(base + KBUFB + key*VSTRB + c8*16,  vh2 + (size_t)(kb+key)*(HDIM/2) + c8*4);
        }
        if (tid < 128) {
            int key = tid >> 1, c2 = tid & 1;
            cp16(base + KBUFB + VBUFB + key*SSTRB + c2*16,
                 ksph + (size_t)(kb+key)*(SDIM/2) + c2*4);
        }
    };

    const int nTiles = (q0 + AQT) / AKT;   // >= 2 always

    // init V pads (cols 64..87) for all 3 buffers: col 64 = 1.0 (never clobbered by cp)
    for (int k = tid; k < NBUF*64*12; k += 256) {
        int buf = k / (64*12);
        int kk = k - buf*(64*12);
        int r = kk / 12, c = kk % 12;
        unsigned val = (c == 0) ? 0x00003C00u : 0u;
        *(unsigned*)((char*)ash + buf*ABUFB + KBUFB + r*VSTRB + 128 + c*4) = val;
    }

    issue_tile(0, 0);
    asm volatile("cp.async.commit_group;");
    issue_tile(AKT, 1);
    asm volatile("cp.async.commit_group;");

    for (int t = 0; t < nTiles; t++) {
        const int kb = t*AKT;
        const int buf = t % NBUF;

        asm volatile("cp.async.wait_group 1;" ::: "memory");
        __syncthreads();

        if (t + 2 < nTiles) issue_tile(kb + 2*AKT, (t + 2) % NBUF);
        asm volatile("cp.async.commit_group;");

        if (kb <= q0w + 15) {
            const unsigned kBase  = shbase + buf*ABUFB;
            const unsigned vBase  = kBase + KBUFB;
            const unsigned spBase = kBase + KBUFB + VBUFB;
            const bool needMask = (kb + AKT - 1 > q0w);

            #pragma unroll
            for (int g2 = 0; g2 < 4; g2++) {
                float s0[4] = {0.f,0.f,0.f,0.f}, s1[4] = {0.f,0.f,0.f,0.f};

                #pragma unroll
                for (int kt = 0; kt < 4; kt++) {
                    uint4 bb = ldsm4(kBase + (g2*16 + kRow)*KSTRB + (kt*16 + kCol)*2);
                    mma_f16(s0[0], s0[1], s0[2], s0[3],
                            qa[kt][0], qa[kt][1], qa[kt][2], qa[kt][3], bb.x, bb.y);
                    mma_f16(s1[0], s1[1], s1[2], s1[3],
                            qa[kt][0], qa[kt][1], qa[kt][2], qa[kt][3], bb.z, bb.w);
                }

                float sp0[4] = {0.f,0.f,0.f,0.f}, sp1[4] = {0.f,0.f,0.f,0.f};
                {
                    uint4 bb = ldsm4(spBase + (g2*16 + kRow)*SSTRB + kCol*2);
                    mma_f16(sp0[0], sp0[1], sp0[2], sp0[3],
                            qsa[0], qsa[1], qsa[2], qsa[3], bb.x, bb.y);
                    mma_f16(sp1[0], sp1[1], sp1[2], sp1[3],
                            qsa[0], qsa[1], qsa[2], qsa[3], bb.z, bb.w);
                }

                unsigned hs[4], hsp[4];
                hs[0] = packh2(s0[0], s0[1]);  hs[1] = packh2(s0[2], s0[3]);
                hs[2] = packh2(s1[0], s1[1]);  hs[3] = packh2(s1[2], s1[3]);
                hsp[0] = packh2(sp0[0], sp0[1]); hsp[1] = packh2(sp0[2], sp0[3]);
                hsp[2] = packh2(sp1[0], sp1[1]); hsp[3] = packh2(sp1[2], sp1[3]);

                unsigned p[4];
                #pragma unroll
                for (int i = 0; i < 4; i++) {
                    unsigned g = h2fma(h2tanh(h2mul(hsp[i], H0125)), H05, H05);
                    p[i] = h2ex2(h2mul(h2mul(hs[i], HCQK), g));
                }

                if (needMask) {
                    int k0 = kb + g2*16 + 2*t4;
                    int k8 = k0 + 8;
                    unsigned m0 = (k0 <= qr0 ? HONE : 0u) | (k0+1 <= qr0 ? (HONE<<16) : 0u);
                    unsigned m1 = (k0 <= qr1 ? HONE : 0u) | (k0+1 <= qr1 ? (HONE<<16) : 0u);
                    unsigned m2 = (k8 <= qr0 ? HONE : 0u) | (k8+1 <= qr0 ? (HONE<<16) : 0u);
                    unsigned m3 = (k8 <= qr1 ? HONE : 0u) | (k8+1 <= qr1 ? (HONE<<16) : 0u);
                    p[0] = h2mul(p[0], m0); p[1] = h2mul(p[1], m1);
                    p[2] = h2mul(p[2], m2); p[3] = h2mul(p[3], m3);
                }

                #pragma unroll
                for (int dnp = 0; dnp < 4; dnp++) {
                    uint4 bb = ldsm4t(vBase + (g2*16 + vRow)*VSTRB + (dnp*16 + vCol)*2);
                    mma_f16(O[2*dnp  ][0], O[2*dnp  ][1], O[2*dnp  ][2], O[2*dnp  ][3],
                            p[0], p[1], p[2], p[3], bb.x, bb.y);
                    mma_f16(O[2*dnp+1][0], O[2*dnp+1][1], O[2*dnp+1][2], O[2*dnp+1][3],
                            p[0], p[1], p[2], p[3], bb.z, bb.w);
                }
                {
                    uint4 bb = ldsm4t(vBase + (g2*16 + vRow)*VSTRB + (4*16 + vCol)*2);
                    mma_f16(Ol[0], Ol[1], Ol[2], Ol[3],
                            p[0], p[1], p[2], p[3], bb.x, bb.y);
                }
            }
        }
    }

    // epilogue: l lives in col 64 (t4==0 lanes); broadcast within quad
    float lsum0 = __shfl_sync(0xffffffffu, Ol[0], lane & ~3);
    float lsum1 = __shfl_sync(0xffffffffu, Ol[2], lane & ~3);
    float inv0 = rcpf(lsum0), inv1 = rcpf(lsum1);
    #pragma unroll
    for (int dn = 0; dn < 8; dn++) {
        int col2 = (h*HDIM + dn*8 + 2*t4) >> 1;
        g_atth[((size_t)b*SS + qr0)*(DD/2) + col2] = packh2(O[dn][0]*inv0, O[dn][1]*inv0);
        g_atth[((size_t)b*SS + qr1)*(DD/2) + col2] = packh2(O[dn][2]*inv1, O[dn][3]*inv1);
    }
}

// ---------------- launch ----------------
extern "C" void kernel_launch(void* const* d_in, const int* in_sizes, int n_in,
                              void* d_out, int out_size)
{
    (void)in_sizes; (void)n_in; (void)out_size;
    const float* x  = (const float*)d_in[0];
    const float* Wq = (const float*)d_in[1];
    const float* Wk = (const float*)d_in[2];
    const float* Wv = (const float*)d_in[3];
    const float* Wo = (const float*)d_in[4];
    const float* bo = (const float*)d_in[5];
    const float* Ws = (const float*)d_in[6];
    const float* bs = (const float*)d_in[7];
    float* out = (float*)d_out;

    float *qlin, *klin, *vlin;
    unsigned *xh, *wqh, *wkh, *wvh, *woh, *atth;
    cudaGetSymbolAddress((void**)&qlin, g_qlin);
    cudaGetSymbolAddress((void**)&klin, g_klin);
    cudaGetSymbolAddress((void**)&vlin, g_vlin);
    cudaGetSymbolAddress((void**)&xh,   g_xh);
    cudaGetSymbolAddress((void**)&wqh,  g_wqh);
    cudaGetSymbolAddress((void**)&wkh,  g_wkh);
    cudaGetSymbolAddress((void**)&wvh,  g_wvh);
    cudaGetSymbolAddress((void**)&woh,  g_woh);
    cudaGetSymbolAddress((void**)&atth, g_atth);

    const int M = BB*SS;   // 4096

    static bool attr_set = false;
    if (!attr_set) {
        cudaFuncSetAttribute(gemm3h, cudaFuncAttributeMaxDynamicSharedMemorySize, GSMEM);
        cudaFuncSetAttribute(attn_mma_kernel, cudaFuncAttributeMaxDynamicSharedMemorySize, ASMEM);
        attr_set = true;
    }

    prep_kernel<<<PREP_BLOCKS, 256>>>(x, Wq, Wk, Wv, Wo);

    gemm3h<<<dim3(12, M/TBM), 256, GSMEM>>>(xh,
                                    wqh, qlin, 8, DD,
                                    wkh, klin, 2, HKV*HDIM,
                                    wvh, vlin, 2, HKV*HDIM,
                                    nullptr, DD);

    rope_sp_all<<<(BB*SS*(HH+HKV) + 255)/256, 256>>>(Ws, bs);

    attn_mma_kernel<<<dim3(SS/AQT, HH, BB), 256, ASMEM>>>();

    gemm3h<<<dim3(8, M/TBM), 256, GSMEM>>>(atth,
                                    woh, out, 8, DD,
                                    nullptr, nullptr, 0, 0,
                                    nullptr, nullptr, 0, 0,
                                    bo, DD);
}